// round 1
// baseline (speedup 1.0000x reference)
#include <cuda_runtime.h>
#include <cuda_bf16.h>

#define MAXN 50000
#define MAXE 800000

__device__ float d_h64[MAXN * 64];
__device__ float d_xl[MAXN * 256];
__device__ float d_xr[MAXN * 256];
__device__ float d_accA[MAXN * 256];
__device__ float d_accB[MAXN * 256];
__device__ float d_den[MAXN * 4];
__device__ float d_deg[MAXN];
__device__ float d_loop[MAXN];
__device__ float d_gsum[64 * 256];
__device__ float d_gcnt[64];

__device__ __forceinline__ void red_add_v4(float* addr, float4 v) {
    asm volatile("red.global.add.v4.f32 [%0], {%1, %2, %3, %4};"
                 :: "l"(addr), "f"(v.x), "f"(v.y), "f"(v.z), "f"(v.w)
                 : "memory");
}

// ---------------- encoder: h = relu(x @ W[4,64] + b) ----------------
__global__ void encoder_kernel(const float* __restrict__ x,
                               const float* __restrict__ w,
                               const float* __restrict__ b,
                               float* __restrict__ h, int N) {
    int idx = blockIdx.x * blockDim.x + threadIdx.x;
    if (idx >= N * 64) return;
    int i = idx >> 6, j = idx & 63;
    float4 xv = *(const float4*)(x + (size_t)i * 4);
    float s = b[j] + xv.x * w[j] + xv.y * w[64 + j] + xv.z * w[128 + j] + xv.w * w[192 + j];
    h[idx] = fmaxf(s, 0.f);
}

// ---------------- degree + self-loop attr ----------------
__global__ void degloop_kernel(const int* __restrict__ ei,
                               const float* __restrict__ eattr,
                               float* __restrict__ deg, float* __restrict__ loopa, int E) {
    int e = blockIdx.x * blockDim.x + threadIdx.x;
    if (e >= E) return;
    int dst = ei[E + e];
    atomicAdd(deg + dst, 1.0f);
    atomicAdd(loopa + dst, eattr[e]);
}

__global__ void loopdiv_kernel(float* __restrict__ loopa, const float* __restrict__ deg, int N) {
    int i = blockIdx.x * blockDim.x + threadIdx.x;
    if (i >= N) return;
    loopa[i] = loopa[i] / fmaxf(deg[i], 1.0f);
}

// ---------------- SGEMM: C[M,256] = A[M,K] @ W[K,256] + bias ----------------
__global__ __launch_bounds__(256) void gemm_bias_kernel(
    const float* __restrict__ A, const float* __restrict__ W,
    const float* __restrict__ bias, float* __restrict__ C,
    int M, int K) {
    const int Nn = 256;
    __shared__ float As[8][128];
    __shared__ float Ws[8][128];
    int tid = threadIdx.x;
    int row0 = blockIdx.y * 128, col0 = blockIdx.x * 128;
    int tx = tid & 15, ty = tid >> 4;
    float acc[8][8];
#pragma unroll
    for (int i = 0; i < 8; i++)
#pragma unroll
        for (int j = 0; j < 8; j++) acc[i][j] = 0.f;

    int ar = tid >> 1, ak = (tid & 1) << 2;
    int wk = tid >> 5, wc = (tid & 31) << 2;
    int grow = row0 + ar;
    const float* Arow = A + (size_t)grow * K;

    for (int k0 = 0; k0 < K; k0 += 8) {
        float4 av = make_float4(0.f, 0.f, 0.f, 0.f);
        if (grow < M) av = *(const float4*)(Arow + k0 + ak);
        As[ak + 0][ar] = av.x; As[ak + 1][ar] = av.y;
        As[ak + 2][ar] = av.z; As[ak + 3][ar] = av.w;
        *(float4*)&Ws[wk][wc] = *(const float4*)(W + (size_t)(k0 + wk) * Nn + col0 + wc);
        __syncthreads();
#pragma unroll
        for (int k = 0; k < 8; k++) {
            float a0[8], w0[8];
            *(float4*)(a0)     = *(float4*)&As[k][ty * 8];
            *(float4*)(a0 + 4) = *(float4*)&As[k][ty * 8 + 4];
            *(float4*)(w0)     = *(float4*)&Ws[k][tx * 8];
            *(float4*)(w0 + 4) = *(float4*)&Ws[k][tx * 8 + 4];
#pragma unroll
            for (int i = 0; i < 8; i++)
#pragma unroll
                for (int j = 0; j < 8; j++)
                    acc[i][j] += a0[i] * w0[j];
        }
        __syncthreads();
    }
    float bj[8];
#pragma unroll
    for (int j = 0; j < 8; j++) bj[j] = bias[col0 + tx * 8 + j];
#pragma unroll
    for (int i = 0; i < 8; i++) {
        int r = row0 + ty * 8 + i;
        if (r < M) {
            float* Crow = C + (size_t)r * Nn + col0 + tx * 8;
#pragma unroll
            for (int j = 0; j < 8; j += 4) {
                float4 v = make_float4(acc[i][j] + bj[j], acc[i][j + 1] + bj[j + 1],
                                       acc[i][j + 2] + bj[j + 2], acc[i][j + 3] + bj[j + 3]);
                *(float4*)(Crow + j) = v;
            }
        }
    }
}

// ---------------- fused edge pass: one warp per edge ----------------
// num[dst] += exp(alpha) * xl[src] ; den[dst,h] += exp(alpha)
__global__ __launch_bounds__(256) void edge_kernel(
    const int* __restrict__ ei, const float* __restrict__ eattr,
    const float* __restrict__ loop_attr,
    const float* __restrict__ xl, const float* __restrict__ xr,
    const float* __restrict__ we, const float* __restrict__ att,
    float* __restrict__ acc, float* __restrict__ den,
    int E, int N) {
    int lane = threadIdx.x & 31;
    int gw = (blockIdx.x * blockDim.x + threadIdx.x) >> 5;
    int nw = (gridDim.x * blockDim.x) >> 5;
    int c0 = lane << 3;     // 8 columns per lane
    int head = lane >> 3;   // 8 lanes per head
    float wef[8], attf[8];
#pragma unroll
    for (int i = 0; i < 8; i++) { wef[i] = we[c0 + i]; attf[i] = att[c0 + i]; }

    int EA = E + N;
    for (int e = gw; e < EA; e += nw) {
        int src, dst; float ea;
        if (e < E) { src = ei[e]; dst = ei[E + e]; ea = eattr[e]; }
        else       { src = e - E; dst = src; ea = loop_attr[src]; }

        const float* pl = xl + (size_t)src * 256 + c0;
        const float* pr = xr + (size_t)dst * 256 + c0;
        float4 l0 = *(const float4*)pl;
        float4 l1 = *(const float4*)(pl + 4);
        float4 r0 = *(const float4*)pr;
        float4 r1 = *(const float4*)(pr + 4);
        float lv[8] = {l0.x, l0.y, l0.z, l0.w, l1.x, l1.y, l1.z, l1.w};
        float rv[8] = {r0.x, r0.y, r0.z, r0.w, r1.x, r1.y, r1.z, r1.w};

        float a = 0.f;
#pragma unroll
        for (int i = 0; i < 8; i++) {
            float m = lv[i] + rv[i] + ea * wef[i];
            m = (m > 0.f) ? m : 0.2f * m;   // leaky_relu 0.2
            a += m * attf[i];
        }
        // reduce over the 8 lanes of this head
        a += __shfl_xor_sync(0xffffffffu, a, 1);
        a += __shfl_xor_sync(0xffffffffu, a, 2);
        a += __shfl_xor_sync(0xffffffffu, a, 4);
        float ex = __expf(a);   // softmax shift-invariant; alpha is small -> safe

        if ((lane & 7) == 0) atomicAdd(den + (size_t)dst * 4 + head, ex);
        float* pa = acc + (size_t)dst * 256 + c0;
        red_add_v4(pa,     make_float4(ex * lv[0], ex * lv[1], ex * lv[2], ex * lv[3]));
        red_add_v4(pa + 4, make_float4(ex * lv[4], ex * lv[5], ex * lv[6], ex * lv[7]));
    }
}

// ---------------- node finalize: h = relu(num/den + bias) (in place) ----------------
__global__ void finalize_kernel(float* __restrict__ acc, const float* __restrict__ den,
                                const float* __restrict__ bias, int N) {
    int idx = blockIdx.x * blockDim.x + threadIdx.x;
    if (idx >= N * 64) return;
    int i = idx >> 6;
    int c4 = (idx & 63) << 2;
    float inv = 1.0f / den[(size_t)i * 4 + (c4 >> 6)];
    float4 a = *(float4*)(acc + (size_t)i * 256 + c4);
    float4 b = *(const float4*)(bias + c4);
    a.x = fmaxf(a.x * inv + b.x, 0.f);
    a.y = fmaxf(a.y * inv + b.y, 0.f);
    a.z = fmaxf(a.z * inv + b.z, 0.f);
    a.w = fmaxf(a.w * inv + b.w, 0.f);
    *(float4*)(acc + (size_t)i * 256 + c4) = a;
}

// ---------------- global mean pool (batch is sorted) ----------------
__global__ __launch_bounds__(256) void pool_kernel(
    const float* __restrict__ h, const int* __restrict__ batch,
    float* __restrict__ gsum, float* __restrict__ gcnt, int N) {
    __shared__ int sb[256];
    int t = threadIdx.x;
    int start = blockIdx.x * 256;
    int end = min(start + 256, N);
    int n = end - start;
    if (n <= 0) return;
    if (t < n) sb[t] = batch[start + t];
    __syncthreads();
    float acc = 0.f, cnt = 0.f;
    int cur = sb[0];
    for (int i = 0; i < n; i++) {
        int b = sb[i];
        if (b != cur) {
            atomicAdd(gsum + (size_t)cur * 256 + t, acc);
            if (t == 0) atomicAdd(gcnt + cur, cnt);
            acc = 0.f; cnt = 0.f; cur = b;
        }
        acc += h[(size_t)(start + i) * 256 + t];
        cnt += 1.f;
    }
    atomicAdd(gsum + (size_t)cur * 256 + t, acc);
    if (t == 0) atomicAdd(gcnt + cur, cnt);
}

// ---------------- final MLP: 256 -> 128 (LN, relu) -> 64 (relu) ----------------
__global__ __launch_bounds__(128) void mlp_kernel(
    const float* __restrict__ gsum, const float* __restrict__ gcnt,
    const float* __restrict__ p1w, const float* __restrict__ p1b,
    const float* __restrict__ lng, const float* __restrict__ lnb,
    const float* __restrict__ p2w, const float* __restrict__ p2b,
    float* __restrict__ out) {
    __shared__ float gs[256];
    __shared__ float zs[128];
    __shared__ float wsum[4], wsum2[4];
    int b = blockIdx.x, t = threadIdx.x;
    float invc = 1.0f / fmaxf(gcnt[b], 1.0f);
    gs[t] = gsum[(size_t)b * 256 + t] * invc;
    gs[t + 128] = gsum[(size_t)b * 256 + 128 + t] * invc;
    __syncthreads();
    float z = p1b[t];
    for (int k = 0; k < 256; k++) z += gs[k] * p1w[(size_t)k * 128 + t];
    float s = z, s2 = z * z;
#pragma unroll
    for (int o = 16; o; o >>= 1) {
        s += __shfl_xor_sync(0xffffffffu, s, o);
        s2 += __shfl_xor_sync(0xffffffffu, s2, o);
    }
    if ((t & 31) == 0) { wsum[t >> 5] = s; wsum2[t >> 5] = s2; }
    __syncthreads();
    s = wsum[0] + wsum[1] + wsum[2] + wsum[3];
    s2 = wsum2[0] + wsum2[1] + wsum2[2] + wsum2[3];
    float mu = s * (1.0f / 128.0f);
    float var = s2 * (1.0f / 128.0f) - mu * mu;
    float zn = (z - mu) * rsqrtf(var + 1e-5f) * lng[t] + lnb[t];
    zs[t] = fmaxf(zn, 0.f);
    __syncthreads();
    if (t < 64) {
        float o = p2b[t];
        for (int j = 0; j < 128; j++) o += zs[j] * p2w[(size_t)j * 64 + t];
        out[(size_t)b * 64 + t] = fmaxf(o, 0.f);
    }
}

extern "C" void kernel_launch(void* const* d_in, const int* in_sizes, int n_in,
                              void* d_out, int out_size) {
    const float* x      = (const float*)d_in[0];
    const int*   ei     = (const int*)d_in[1];
    const float* eattr  = (const float*)d_in[2];
    const int*   batch  = (const int*)d_in[3];
    const float* enc_w  = (const float*)d_in[4];
    const float* enc_b  = (const float*)d_in[5];
    const float* g1_wl  = (const float*)d_in[6];
    const float* g1_bl  = (const float*)d_in[7];
    const float* g1_wr  = (const float*)d_in[8];
    const float* g1_br  = (const float*)d_in[9];
    const float* g1_we  = (const float*)d_in[10];
    const float* g1_att = (const float*)d_in[11];
    const float* g1_bias= (const float*)d_in[12];
    const float* g2_wl  = (const float*)d_in[13];
    const float* g2_bl  = (const float*)d_in[14];
    const float* g2_wr  = (const float*)d_in[15];
    const float* g2_br  = (const float*)d_in[16];
    const float* g2_we  = (const float*)d_in[17];
    const float* g2_att = (const float*)d_in[18];
    const float* g2_bias= (const float*)d_in[19];
    const float* p1_w   = (const float*)d_in[20];
    const float* p1_b   = (const float*)d_in[21];
    const float* ln_g   = (const float*)d_in[22];
    const float* ln_b   = (const float*)d_in[23];
    const float* p2_w   = (const float*)d_in[24];
    const float* p2_b   = (const float*)d_in[25];

    int N = in_sizes[3];      // batch vector length = node count
    int E = in_sizes[2];      // edge_attr count = edge count
    int NG_ = out_size / 64;

    float *h64, *xl, *xr, *accA, *accB, *den, *deg, *loopa, *gsum, *gcnt;
    cudaGetSymbolAddress((void**)&h64, d_h64);
    cudaGetSymbolAddress((void**)&xl, d_xl);
    cudaGetSymbolAddress((void**)&xr, d_xr);
    cudaGetSymbolAddress((void**)&accA, d_accA);
    cudaGetSymbolAddress((void**)&accB, d_accB);
    cudaGetSymbolAddress((void**)&den, d_den);
    cudaGetSymbolAddress((void**)&deg, d_deg);
    cudaGetSymbolAddress((void**)&loopa, d_loop);
    cudaGetSymbolAddress((void**)&gsum, d_gsum);
    cudaGetSymbolAddress((void**)&gcnt, d_gcnt);

    cudaMemsetAsync(deg, 0, (size_t)N * sizeof(float));
    cudaMemsetAsync(loopa, 0, (size_t)N * sizeof(float));
    encoder_kernel<<<(N * 64 + 255) / 256, 256>>>(x, enc_w, enc_b, h64, N);
    degloop_kernel<<<(E + 255) / 256, 256>>>(ei, eattr, deg, loopa, E);
    loopdiv_kernel<<<(N + 255) / 256, 256>>>(loopa, deg, N);

    dim3 ggrid(2, (N + 127) / 128);

    // ---- GAT layer 1 (K = 64) ----
    gemm_bias_kernel<<<ggrid, 256>>>(h64, g1_wl, g1_bl, xl, N, 64);
    gemm_bias_kernel<<<ggrid, 256>>>(h64, g1_wr, g1_br, xr, N, 64);
    cudaMemsetAsync(accA, 0, (size_t)N * 256 * sizeof(float));
    cudaMemsetAsync(den, 0, (size_t)N * 4 * sizeof(float));
    edge_kernel<<<4096, 256>>>(ei, eattr, loopa, xl, xr, g1_we, g1_att, accA, den, E, N);
    finalize_kernel<<<(N * 64 + 255) / 256, 256>>>(accA, den, g1_bias, N);

    // ---- GAT layer 2 (K = 256) ----
    gemm_bias_kernel<<<ggrid, 256>>>(accA, g2_wl, g2_bl, xl, N, 256);
    gemm_bias_kernel<<<ggrid, 256>>>(accA, g2_wr, g2_br, xr, N, 256);
    cudaMemsetAsync(accB, 0, (size_t)N * 256 * sizeof(float));
    cudaMemsetAsync(den, 0, (size_t)N * 4 * sizeof(float));
    edge_kernel<<<4096, 256>>>(ei, eattr, loopa, xl, xr, g2_we, g2_att, accB, den, E, N);
    finalize_kernel<<<(N * 64 + 255) / 256, 256>>>(accB, den, g2_bias, N);

    // ---- pool + MLP ----
    cudaMemsetAsync(gsum, 0, (size_t)NG_ * 256 * sizeof(float));
    cudaMemsetAsync(gcnt, 0, (size_t)NG_ * sizeof(float));
    pool_kernel<<<(N + 255) / 256, 256>>>(accB, batch, gsum, gcnt, N);
    mlp_kernel<<<NG_, 128>>>(gsum, gcnt, p1_w, p1_b, ln_g, ln_b, p2_w, p2_b, (float*)d_out);
}

// round 3
// speedup vs baseline: 1.2545x; 1.2545x over previous
#include <cuda_runtime.h>
#include <cuda_bf16.h>

#define MAXN 50000
#define MAXE 800000

__device__ float d_h64[MAXN * 64];
__device__ float d_xl[MAXN * 256];
__device__ float d_xr[MAXN * 256];
__device__ float d_h1[MAXN * 256];
__device__ float d_h2[MAXN * 256];
__device__ int   d_cnt[MAXN];
__device__ float d_loopsum[MAXN];
__device__ float d_loopa[MAXN];
__device__ int   d_rowptr[MAXN + 1];
__device__ int   d_pos[MAXN];
__device__ int   d_csrc[MAXE];
__device__ float d_cea[MAXE];
__device__ float d_gsum[64 * 256];
__device__ float d_gcnt[64];

// ---------------- f32x2 packed helpers ----------------
__device__ __forceinline__ unsigned long long pack2(float a, float b) {
    unsigned long long r;
    asm("mov.b64 %0, {%1, %2};" : "=l"(r) : "f"(a), "f"(b));
    return r;
}
__device__ __forceinline__ void ffma2(unsigned long long& d, unsigned long long a,
                                      unsigned long long b) {
    asm("fma.rn.f32x2 %0, %1, %2, %0;" : "+l"(d) : "l"(a), "l"(b));
}
__device__ __forceinline__ void unpack2(unsigned long long v, float& lo, float& hi) {
    asm("mov.b64 {%0, %1}, %2;" : "=f"(lo), "=f"(hi) : "l"(v));
}

// ---------------- encoder: h = relu(x @ W[4,64] + b) ----------------
__global__ void encoder_kernel(const float* __restrict__ x,
                               const float* __restrict__ w,
                               const float* __restrict__ b,
                               float* __restrict__ h, int N) {
    int idx = blockIdx.x * blockDim.x + threadIdx.x;
    if (idx >= N * 64) return;
    int i = idx >> 6, j = idx & 63;
    float4 xv = *(const float4*)(x + (size_t)i * 4);
    float s = b[j] + xv.x * w[j] + xv.y * w[64 + j] + xv.z * w[128 + j] + xv.w * w[192 + j];
    h[idx] = fmaxf(s, 0.f);
}

// ---------------- CSR build pass 1: count + loop-attr sum ----------------
__global__ void count_kernel(const int* __restrict__ ei,
                             const float* __restrict__ eattr,
                             int* __restrict__ cnt, float* __restrict__ loopsum, int E) {
    int e = blockIdx.x * blockDim.x + threadIdx.x;
    if (e >= E) return;
    int dst = ei[E + e];
    atomicAdd(cnt + dst, 1);
    atomicAdd(loopsum + dst, eattr[e]);
}

// ---------------- CSR build pass 2: single-block exclusive scan ----------------
__global__ __launch_bounds__(1024) void scan_kernel(
    const int* __restrict__ cnt, const float* __restrict__ loopsum,
    int* __restrict__ rowptr, int* __restrict__ pos, float* __restrict__ loopa,
    int N, int E) {
    __shared__ int part[1024];
    int t = threadIdx.x;
    int chunk = (N + 1023) / 1024;
    int b0 = t * chunk, b1 = min(b0 + chunk, N);
    int s = 0;
    for (int j = b0; j < b1; j++) s += cnt[j];
    part[t] = s;
    __syncthreads();
    for (int off = 1; off < 1024; off <<= 1) {
        int v = (t >= off) ? part[t - off] : 0;
        __syncthreads();
        part[t] += v;
        __syncthreads();
    }
    int run = (t == 0) ? 0 : part[t - 1];
    for (int j = b0; j < b1; j++) {
        rowptr[j] = run;
        pos[j] = run;
        int c = cnt[j];
        loopa[j] = loopsum[j] / (float)max(c, 1);
        run += c;
    }
    if (t == 1023) rowptr[N] = E;
}

// ---------------- CSR build pass 3: scatter ----------------
__global__ void scatter_kernel(const int* __restrict__ ei,
                               const float* __restrict__ eattr,
                               int* __restrict__ pos,
                               int* __restrict__ csrc, float* __restrict__ cea, int E) {
    int e = blockIdx.x * blockDim.x + threadIdx.x;
    if (e >= E) return;
    int dst = ei[E + e];
    int p = atomicAdd(pos + dst, 1);
    csrc[p] = ei[e];
    cea[p] = eattr[e];
}

// ---------------- dual SGEMM: xl = A@wl+bl, xr = A@wr+br  (f32x2 packed) ----------------
__global__ __launch_bounds__(256, 2) void gemm_dual_kernel(
    const float* __restrict__ A,
    const float* __restrict__ wl, const float* __restrict__ bl,
    const float* __restrict__ wr, const float* __restrict__ br,
    float* __restrict__ xl, float* __restrict__ xr,
    int M, int K) {
    const int Nn = 256;
    __shared__ float As[8][128];
    __shared__ float Ws[8][128];
    int tid = threadIdx.x;
    int sel = blockIdx.x >> 1;                 // 0 -> wl/xl, 1 -> wr/xr
    const float* W = sel ? wr : wl;
    const float* bias = sel ? br : bl;
    float* C = sel ? xr : xl;
    int col0 = (blockIdx.x & 1) * 128;
    int row0 = blockIdx.y * 128;
    int tx = tid & 15, ty = tid >> 4;

    unsigned long long acc2[8][4];
#pragma unroll
    for (int i = 0; i < 8; i++)
#pragma unroll
        for (int j = 0; j < 4; j++) acc2[i][j] = 0ull;

    int ar = tid >> 1, ak = (tid & 1) << 2;
    int wk = tid >> 5, wc = (tid & 31) << 2;
    int grow = row0 + ar;
    const float* Arow = A + (size_t)grow * K;

    for (int k0 = 0; k0 < K; k0 += 8) {
        float4 av = make_float4(0.f, 0.f, 0.f, 0.f);
        if (grow < M) av = *(const float4*)(Arow + k0 + ak);
        As[ak + 0][ar] = av.x; As[ak + 1][ar] = av.y;
        As[ak + 2][ar] = av.z; As[ak + 3][ar] = av.w;
        *(float4*)&Ws[wk][wc] = *(const float4*)(W + (size_t)(k0 + wk) * Nn + col0 + wc);
        __syncthreads();
#pragma unroll
        for (int k = 0; k < 8; k++) {
            float a0[8];
            unsigned long long w2[4];
            *(float4*)(a0)     = *(float4*)&As[k][ty * 8];
            *(float4*)(a0 + 4) = *(float4*)&As[k][ty * 8 + 4];
            *(float4*)(&w2[0]) = *(float4*)&Ws[k][tx * 8];
            *(float4*)(&w2[2]) = *(float4*)&Ws[k][tx * 8 + 4];
            unsigned long long a2[8];
#pragma unroll
            for (int i = 0; i < 8; i++) a2[i] = pack2(a0[i], a0[i]);
#pragma unroll
            for (int i = 0; i < 8; i++)
#pragma unroll
                for (int j = 0; j < 4; j++)
                    ffma2(acc2[i][j], a2[i], w2[j]);
        }
        __syncthreads();
    }
    float bj[8];
#pragma unroll
    for (int j = 0; j < 8; j++) bj[j] = bias[col0 + tx * 8 + j];
#pragma unroll
    for (int i = 0; i < 8; i++) {
        int r = row0 + ty * 8 + i;
        if (r < M) {
            float out[8];
#pragma unroll
            for (int j = 0; j < 4; j++) {
                unpack2(acc2[i][j], out[2 * j], out[2 * j + 1]);
                out[2 * j] += bj[2 * j];
                out[2 * j + 1] += bj[2 * j + 1];
            }
            float* Crow = C + (size_t)r * Nn + col0 + tx * 8;
            *(float4*)(Crow)     = *(float4*)(out);
            *(float4*)(Crow + 4) = *(float4*)(out + 4);
        }
    }
}

// ---------------- CSR edge pass: one warp per dst node, fully fused ----------------
// out[i] = relu( (sum_e exp(alpha_e) * xl[src_e]) / (sum_e exp(alpha_e)) + bias )
__global__ __launch_bounds__(256) void edge_csr_kernel(
    const int* __restrict__ rowptr, const int* __restrict__ csrc,
    const float* __restrict__ cea, const float* __restrict__ loopa,
    const float* __restrict__ xl, const float* __restrict__ xr,
    const float* __restrict__ we, const float* __restrict__ att,
    const float* __restrict__ bias, float* __restrict__ out, int N) {
    int lane = threadIdx.x & 31;
    int warp = (blockIdx.x * blockDim.x + threadIdx.x) >> 5;
    int nw = (gridDim.x * blockDim.x) >> 5;
    int c0 = lane << 3;
    float wef[8], attf[8], bf[8];
#pragma unroll
    for (int q = 0; q < 8; q++) {
        wef[q] = we[c0 + q]; attf[q] = att[c0 + q]; bf[q] = bias[c0 + q];
    }

    for (int i = warp; i < N; i += nw) {
        const float* pr = xr + (size_t)i * 256 + c0;
        float4 r0 = *(const float4*)pr;
        float4 r1 = *(const float4*)(pr + 4);
        float rv[8] = {r0.x, r0.y, r0.z, r0.w, r1.x, r1.y, r1.z, r1.w};
        float acc[8] = {0, 0, 0, 0, 0, 0, 0, 0};
        float den = 0.f;

        int rb = rowptr[i], re = rowptr[i + 1];
        // current edge = self loop
        float ea = loopa[i];
        const float* pl = xl + (size_t)i * 256 + c0;
        float4 a0 = *(const float4*)pl;
        float4 a1 = *(const float4*)(pl + 4);

        int j = rb;
        while (true) {
            // software-pipeline: issue next edge's loads before computing current
            bool has = (j < re);
            float4 b0, b1; float ean = 0.f;
            if (has) {
                int sn = csrc[j];
                ean = cea[j];
                const float* pn = xl + (size_t)sn * 256 + c0;
                b0 = *(const float4*)pn;
                b1 = *(const float4*)(pn + 4);
            }
            float lv[8] = {a0.x, a0.y, a0.z, a0.w, a1.x, a1.y, a1.z, a1.w};
            float a = 0.f;
#pragma unroll
            for (int q = 0; q < 8; q++) {
                float m = lv[q] + rv[q] + ea * wef[q];
                m = (m > 0.f) ? m : 0.2f * m;      // leaky_relu 0.2
                a += m * attf[q];
            }
            a += __shfl_xor_sync(0xffffffffu, a, 1);
            a += __shfl_xor_sync(0xffffffffu, a, 2);
            a += __shfl_xor_sync(0xffffffffu, a, 4);
            float ex = __expf(a);                  // softmax shift-invariant; alpha small
            den += ex;
#pragma unroll
            for (int q = 0; q < 8; q++) acc[q] += ex * lv[q];
            if (!has) break;
            a0 = b0; a1 = b1; ea = ean; j++;
        }

        float inv = 1.0f / den;                    // den > 0 (self loop always present)
        float o[8];
#pragma unroll
        for (int q = 0; q < 8; q++) o[q] = fmaxf(acc[q] * inv + bf[q], 0.f);
        float* po = out + (size_t)i * 256 + c0;
        *(float4*)(po)     = *(float4*)(o);
        *(float4*)(po + 4) = *(float4*)(o + 4);
    }
}

// ---------------- global mean pool (batch is sorted) ----------------
__global__ __launch_bounds__(256) void pool_kernel(
    const float* __restrict__ h, const int* __restrict__ batch,
    float* __restrict__ gsum, float* __restrict__ gcnt, int N) {
    __shared__ int sb[256];
    int t = threadIdx.x;
    int start = blockIdx.x * 256;
    int end = min(start + 256, N);
    int n = end - start;
    if (n <= 0) return;
    if (t < n) sb[t] = batch[start + t];
    __syncthreads();
    float acc = 0.f, cnt = 0.f;
    int cur = sb[0];
    for (int i = 0; i < n; i++) {
        int b = sb[i];
        if (b != cur) {
            atomicAdd(gsum + (size_t)cur * 256 + t, acc);
            if (t == 0) atomicAdd(gcnt + cur, cnt);
            acc = 0.f; cnt = 0.f; cur = b;
        }
        acc += h[(size_t)(start + i) * 256 + t];
        cnt += 1.f;
    }
    atomicAdd(gsum + (size_t)cur * 256 + t, acc);
    if (t == 0) atomicAdd(gcnt + cur, cnt);
}

// ---------------- final MLP: 256 -> 128 (LN, relu) -> 64 (relu) ----------------
__global__ __launch_bounds__(128) void mlp_kernel(
    const float* __restrict__ gsum, const float* __restrict__ gcnt,
    const float* __restrict__ p1w, const float* __restrict__ p1b,
    const float* __restrict__ lng, const float* __restrict__ lnb,
    const float* __restrict__ p2w, const float* __restrict__ p2b,
    float* __restrict__ out) {
    __shared__ float gs[256];
    __shared__ float zs[128];
    __shared__ float wsum[4], wsum2[4];
    int b = blockIdx.x, t = threadIdx.x;
    float invc = 1.0f / fmaxf(gcnt[b], 1.0f);
    gs[t] = gsum[(size_t)b * 256 + t] * invc;
    gs[t + 128] = gsum[(size_t)b * 256 + 128 + t] * invc;
    __syncthreads();
    float z = p1b[t];
    for (int k = 0; k < 256; k++) z += gs[k] * p1w[(size_t)k * 128 + t];
    float s = z, s2 = z * z;
#pragma unroll
    for (int o = 16; o; o >>= 1) {
        s += __shfl_xor_sync(0xffffffffu, s, o);
        s2 += __shfl_xor_sync(0xffffffffu, s2, o);
    }
    if ((t & 31) == 0) { wsum[t >> 5] = s; wsum2[t >> 5] = s2; }
    __syncthreads();
    s = wsum[0] + wsum[1] + wsum[2] + wsum[3];
    s2 = wsum2[0] + wsum2[1] + wsum2[2] + wsum2[3];
    float mu = s * (1.0f / 128.0f);
    float var = s2 * (1.0f / 128.0f) - mu * mu;
    float zn = (z - mu) * rsqrtf(var + 1e-5f) * lng[t] + lnb[t];
    zs[t] = fmaxf(zn, 0.f);
    __syncthreads();
    if (t < 64) {
        float o = p2b[t];
        for (int j = 0; j < 128; j++) o += zs[j] * p2w[(size_t)j * 64 + t];
        out[(size_t)b * 64 + t] = fmaxf(o, 0.f);
    }
}

extern "C" void kernel_launch(void* const* d_in, const int* in_sizes, int n_in,
                              void* d_out, int out_size) {
    const float* x      = (const float*)d_in[0];
    const int*   ei     = (const int*)d_in[1];
    const float* eattr  = (const float*)d_in[2];
    const int*   batch  = (const int*)d_in[3];
    const float* enc_w  = (const float*)d_in[4];
    const float* enc_b  = (const float*)d_in[5];
    const float* g1_wl  = (const float*)d_in[6];
    const float* g1_bl  = (const float*)d_in[7];
    const float* g1_wr  = (const float*)d_in[8];
    const float* g1_br  = (const float*)d_in[9];
    const float* g1_we  = (const float*)d_in[10];
    const float* g1_att = (const float*)d_in[11];
    const float* g1_bias= (const float*)d_in[12];
    const float* g2_wl  = (const float*)d_in[13];
    const float* g2_bl  = (const float*)d_in[14];
    const float* g2_wr  = (const float*)d_in[15];
    const float* g2_br  = (const float*)d_in[16];
    const float* g2_we  = (const float*)d_in[17];
    const float* g2_att = (const float*)d_in[18];
    const float* g2_bias= (const float*)d_in[19];
    const float* p1_w   = (const float*)d_in[20];
    const float* p1_b   = (const float*)d_in[21];
    const float* ln_g   = (const float*)d_in[22];
    const float* ln_b   = (const float*)d_in[23];
    const float* p2_w   = (const float*)d_in[24];
    const float* p2_b   = (const float*)d_in[25];

    int N = in_sizes[3];
    int E = in_sizes[2];
    int NG_ = out_size / 64;

    float *h64, *xl, *xr, *h1, *h2, *loopsum, *loopa, *cea, *gsum, *gcnt;
    int *cnt, *rowptr, *pos, *csrc;
    cudaGetSymbolAddress((void**)&h64, d_h64);
    cudaGetSymbolAddress((void**)&xl, d_xl);
    cudaGetSymbolAddress((void**)&xr, d_xr);
    cudaGetSymbolAddress((void**)&h1, d_h1);
    cudaGetSymbolAddress((void**)&h2, d_h2);
    cudaGetSymbolAddress((void**)&cnt, d_cnt);
    cudaGetSymbolAddress((void**)&loopsum, d_loopsum);
    cudaGetSymbolAddress((void**)&loopa, d_loopa);
    cudaGetSymbolAddress((void**)&rowptr, d_rowptr);
    cudaGetSymbolAddress((void**)&pos, d_pos);
    cudaGetSymbolAddress((void**)&csrc, d_csrc);
    cudaGetSymbolAddress((void**)&cea, d_cea);
    cudaGetSymbolAddress((void**)&gsum, d_gsum);
    cudaGetSymbolAddress((void**)&gcnt, d_gcnt);

    // ---- CSR build (once, shared by both layers) ----
    cudaMemsetAsync(cnt, 0, (size_t)N * sizeof(int));
    cudaMemsetAsync(loopsum, 0, (size_t)N * sizeof(float));
    encoder_kernel<<<(N * 64 + 255) / 256, 256>>>(x, enc_w, enc_b, h64, N);
    count_kernel<<<(E + 255) / 256, 256>>>(ei, eattr, cnt, loopsum, E);
    scan_kernel<<<1, 1024>>>(cnt, loopsum, rowptr, pos, loopa, N, E);
    scatter_kernel<<<(E + 255) / 256, 256>>>(ei, eattr, pos, csrc, cea, E);

    dim3 ggrid(4, (N + 127) / 128);
    int eblocks = (N * 32 + 255) / 256;

    // ---- GAT layer 1 (K = 64) ----
    gemm_dual_kernel<<<ggrid, 256>>>(h64, g1_wl, g1_bl, g1_wr, g1_br, xl, xr, N, 64);
    edge_csr_kernel<<<eblocks, 256>>>(rowptr, csrc, cea, loopa, xl, xr,
                                      g1_we, g1_att, g1_bias, h1, N);

    // ---- GAT layer 2 (K = 256) ----
    gemm_dual_kernel<<<ggrid, 256>>>(h1, g2_wl, g2_bl, g2_wr, g2_br, xl, xr, N, 256);
    edge_csr_kernel<<<eblocks, 256>>>(rowptr, csrc, cea, loopa, xl, xr,
                                      g2_we, g2_att, g2_bias, h2, N);

    // ---- pool + MLP ----
    cudaMemsetAsync(gsum, 0, (size_t)NG_ * 256 * sizeof(float));
    cudaMemsetAsync(gcnt, 0, (size_t)NG_ * sizeof(float));
    pool_kernel<<<(N + 255) / 256, 256>>>(h2, batch, gsum, gcnt, N);
    mlp_kernel<<<NG_, 128>>>(gsum, gcnt, p1_w, p1_b, ln_g, ln_b, p2_w, p2_b, (float*)d_out);
}

// round 6
// speedup vs baseline: 1.4234x; 1.1346x over previous
#include <cuda_runtime.h>
#include <cuda_bf16.h>
#include <cstdint>

#define MAXN 50000
#define MAXE 800000
#define MAXT 391            // ceil(MAXN/128)

// ---------------- device scratch ----------------
__device__ float d_h64[MAXN * 64];
__device__ float d_xl[MAXN * 256];
__device__ float d_xr[MAXN * 256];
__device__ float d_h1[MAXN * 256];
__device__ float d_h2[MAXN * 256];
__device__ int   d_cnt[MAXN];
__device__ float d_loopsum[MAXN];
__device__ float d_loopa[MAXN];
__device__ int   d_rowptr[MAXN + 1];
__device__ int   d_pos[MAXN];
__device__ int   d_csrc[MAXE];
__device__ float d_cea[MAXE];
__device__ float d_gsum[64 * 256];
__device__ float d_gcnt[64];
// bf16 hi/lo images, padded to full 128-row tiles
__device__ __align__(16) unsigned short d_ahi[MAXT * 128 * 256];
__device__ __align__(16) unsigned short d_alo[MAXT * 128 * 256];
// transposed combined weights Wt[n][k] (n: 0-255 = wl cols, 256-511 = wr cols)
__device__ __align__(16) unsigned short d_w1hi[512 * 64],  d_w1lo[512 * 64];
__device__ __align__(16) unsigned short d_w2hi[512 * 256], d_w2lo[512 * 256];

// ---------------- helpers ----------------
__device__ __forceinline__ uint32_t smem_u32(const void* p) {
    uint32_t a;
    asm("{ .reg .u64 t; cvta.to.shared.u64 t, %1; cvt.u32.u64 %0, t; }" : "=r"(a) : "l"(p));
    return a;
}
__device__ __forceinline__ void ldsm4(uint32_t* r, uint32_t addr) {
    asm volatile("ldmatrix.sync.aligned.m8n8.x4.shared.b16 {%0,%1,%2,%3}, [%4];"
                 : "=r"(r[0]), "=r"(r[1]), "=r"(r[2]), "=r"(r[3]) : "r"(addr));
}
__device__ __forceinline__ void mma_bf16(float* c, const uint32_t* a, uint32_t b0, uint32_t b1) {
    asm volatile("mma.sync.aligned.m16n8k16.row.col.f32.bf16.bf16.f32 "
                 "{%0,%1,%2,%3}, {%4,%5,%6,%7}, {%8,%9}, {%0,%1,%2,%3};"
                 : "+f"(c[0]), "+f"(c[1]), "+f"(c[2]), "+f"(c[3])
                 : "r"(a[0]), "r"(a[1]), "r"(a[2]), "r"(a[3]), "r"(b0), "r"(b1));
}
__device__ __forceinline__ void split_bf16(float v, unsigned short& h, unsigned short& l) {
    __nv_bfloat16 hb = __float2bfloat16_rn(v);
    float r = v - __bfloat162float(hb);
    __nv_bfloat16 lb = __float2bfloat16_rn(r);
    h = __bfloat16_as_ushort(hb);
    l = __bfloat16_as_ushort(lb);
}

// ---------------- encoder: h = relu(x @ W[4,64] + b) ----------------
__global__ void encoder_kernel(const float* __restrict__ x,
                               const float* __restrict__ w,
                               const float* __restrict__ b,
                               float* __restrict__ h, int N) {
    int idx = blockIdx.x * blockDim.x + threadIdx.x;
    if (idx >= N * 64) return;
    int i = idx >> 6, j = idx & 63;
    float4 xv = *(const float4*)(x + (size_t)i * 4);
    float s = b[j] + xv.x * w[j] + xv.y * w[64 + j] + xv.z * w[128 + j] + xv.w * w[192 + j];
    h[idx] = fmaxf(s, 0.f);
}

// ---------------- CSR build ----------------
__global__ void count_kernel(const int* __restrict__ ei, const float* __restrict__ eattr,
                             int* __restrict__ cnt, float* __restrict__ loopsum, int E) {
    int e = blockIdx.x * blockDim.x + threadIdx.x;
    if (e >= E) return;
    int dst = ei[E + e];
    atomicAdd(cnt + dst, 1);
    atomicAdd(loopsum + dst, eattr[e]);
}

__global__ __launch_bounds__(1024) void scan_kernel(
    const int* __restrict__ cnt, const float* __restrict__ loopsum,
    int* __restrict__ rowptr, int* __restrict__ pos, float* __restrict__ loopa,
    int N, int E) {
    __shared__ int part[1024];
    int t = threadIdx.x;
    int chunk = (N + 1023) / 1024;
    int b0 = t * chunk, b1 = min(b0 + chunk, N);
    int s = 0;
    for (int j = b0; j < b1; j++) s += cnt[j];
    part[t] = s;
    __syncthreads();
    for (int off = 1; off < 1024; off <<= 1) {
        int v = (t >= off) ? part[t - off] : 0;
        __syncthreads();
        part[t] += v;
        __syncthreads();
    }
    int run = (t == 0) ? 0 : part[t - 1];
    for (int j = b0; j < b1; j++) {
        rowptr[j] = run;
        pos[j] = run;
        int c = cnt[j];
        loopa[j] = loopsum[j] / (float)max(c, 1);
        run += c;
    }
    if (t == 1023) rowptr[N] = E;
}

__global__ void scatter_kernel(const int* __restrict__ ei, const float* __restrict__ eattr,
                               int* __restrict__ pos,
                               int* __restrict__ csrc, float* __restrict__ cea, int E) {
    int e = blockIdx.x * blockDim.x + threadIdx.x;
    if (e >= E) return;
    int dst = ei[E + e];
    int p = atomicAdd(pos + dst, 1);
    csrc[p] = ei[e];
    cea[p] = eattr[e];
}

// ---------------- A fp32 [M,K] -> bf16 hi/lo (row-major) ----------------
__global__ void conv_a_kernel(const float* __restrict__ A, int M, int K,
                              unsigned short* __restrict__ hi, unsigned short* __restrict__ lo) {
    int total = M * (K >> 3);
    int gid = blockIdx.x * blockDim.x + threadIdx.x;
    if (gid >= total) return;
    size_t off = (size_t)gid * 8;
    float4 f0 = *(const float4*)(A + off);
    float4 f1 = *(const float4*)(A + off + 4);
    float v[8] = {f0.x, f0.y, f0.z, f0.w, f1.x, f1.y, f1.z, f1.w};
    uint32_t hv[4], lv[4];
#pragma unroll
    for (int q = 0; q < 4; q++) {
        unsigned short h0, l0, h1, l1;
        split_bf16(v[2 * q], h0, l0);
        split_bf16(v[2 * q + 1], h1, l1);
        hv[q] = (uint32_t)h0 | ((uint32_t)h1 << 16);
        lv[q] = (uint32_t)l0 | ((uint32_t)l1 << 16);
    }
    *(uint4*)(hi + off) = make_uint4(hv[0], hv[1], hv[2], hv[3]);
    *(uint4*)(lo + off) = make_uint4(lv[0], lv[1], lv[2], lv[3]);
}

// ---------------- W [K,256] x2 -> combined transposed Wt[n][k] bf16 hi/lo ----------------
__global__ void conv_w_kernel(const float* __restrict__ wl, const float* __restrict__ wr,
                              int K,
                              unsigned short* __restrict__ hi, unsigned short* __restrict__ lo) {
    int gpr = K >> 3;
    int total = 512 * gpr;
    int gid = blockIdx.x * blockDim.x + threadIdx.x;
    if (gid >= total) return;
    int n = gid / gpr, g = gid % gpr;
    int ks = g * 8;
    const float* src = (n < 256) ? wl : wr;
    int col = n & 255;
    uint32_t hv[4], lv[4];
#pragma unroll
    for (int q = 0; q < 4; q++) {
        float v0 = src[(size_t)(ks + 2 * q) * 256 + col];
        float v1 = src[(size_t)(ks + 2 * q + 1) * 256 + col];
        unsigned short h0, l0, h1, l1;
        split_bf16(v0, h0, l0);
        split_bf16(v1, h1, l1);
        hv[q] = (uint32_t)h0 | ((uint32_t)h1 << 16);
        lv[q] = (uint32_t)l0 | ((uint32_t)l1 << 16);
    }
    size_t off = (size_t)n * K + ks;
    *(uint4*)(hi + off) = make_uint4(hv[0], hv[1], hv[2], hv[3]);
    *(uint4*)(lo + off) = make_uint4(lv[0], lv[1], lv[2], lv[3]);
}

// ---------------- mma.sync dual GEMM ----------------
// C[M,512] = A[M,K] @ Wt^T + bias  (split-bf16: Ahi*Whi + Ahi*Wlo + Alo*Whi)
// cols 0-255 -> xl, 256-511 -> xr. CTA tile 128x128, warp tile 32x64, BK=16.
#define SROW 24   // ushorts per smem row (48B stride, conflict-free for ldmatrix)
__global__ __launch_bounds__(256) void gemm_mma_kernel(
    const unsigned short* __restrict__ ahi, const unsigned short* __restrict__ alo,
    const unsigned short* __restrict__ whi, const unsigned short* __restrict__ wlo,
    const float* __restrict__ bl, const float* __restrict__ br,
    float* __restrict__ xl, float* __restrict__ xr, int M, int K) {
    __shared__ __align__(16) unsigned short sAh[128 * SROW], sAl[128 * SROW];
    __shared__ __align__(16) unsigned short sBh[128 * SROW], sBl[128 * SROW];

    int tid = threadIdx.x, lane = tid & 31, wid = tid >> 5;
    int wm = wid & 3, wn = wid >> 2;
    int row0 = blockIdx.y * 128, bn0 = blockIdx.x * 128;

    float acc[2][8][4];
#pragma unroll
    for (int t = 0; t < 2; t++)
#pragma unroll
        for (int j = 0; j < 8; j++)
#pragma unroll
            for (int q = 0; q < 4; q++) acc[t][j][q] = 0.f;

    // staging: thread -> (row = tid/2, khalf = tid%2)
    int srow = tid >> 1, kh = (tid & 1) << 3;
    int sidx = srow * 3 + (tid & 1);           // uint4 index (stride 3 per row)
    const int nstage = K >> 4;

    uint32_t aAh = smem_u32(sAh), aAl = smem_u32(sAl);
    uint32_t aBh = smem_u32(sBh), aBl = smem_u32(sBl);

    // ldmatrix lane addresses
    uint32_t aoff = (uint32_t)((lane & 15) * 48 + ((lane >> 4) << 4));
    uint32_t boff = (uint32_t)((((lane >> 4) << 3) + (lane & 7)) * 48 + (((lane >> 3) & 1) << 4));

    size_t gA = (size_t)(row0 + srow) * K + kh;
    size_t gB = (size_t)(bn0 + srow) * K + kh;

    uint4 rAh = *(const uint4*)(ahi + gA);
    uint4 rAl = *(const uint4*)(alo + gA);
    uint4 rBh = *(const uint4*)(whi + gB);
    uint4 rBl = *(const uint4*)(wlo + gB);

    for (int s = 0; s < nstage; s++) {
        ((uint4*)sAh)[sidx] = rAh;
        ((uint4*)sAl)[sidx] = rAl;
        ((uint4*)sBh)[sidx] = rBh;
        ((uint4*)sBl)[sidx] = rBl;
        __syncthreads();
        if (s + 1 < nstage) {
            size_t o = (size_t)(s + 1) * 16;
            rAh = *(const uint4*)(ahi + gA + o);
            rAl = *(const uint4*)(alo + gA + o);
            rBh = *(const uint4*)(whi + gB + o);
            rBl = *(const uint4*)(wlo + gB + o);
        }

        uint32_t a_hi[2][4], a_lo[2][4];
#pragma unroll
        for (int t = 0; t < 2; t++) {
            uint32_t ra = (uint32_t)((wm * 32 + t * 16) * 48);
            ldsm4(a_hi[t], aAh + ra + aoff);
            ldsm4(a_lo[t], aAl + ra + aoff);
        }
#pragma unroll
        for (int bp = 0; bp < 4; bp++) {
            uint32_t rb = (uint32_t)((wn * 64 + bp * 16) * 48);
            uint32_t bh[4], blo[4];
            ldsm4(bh, aBh + rb + boff);
            ldsm4(blo, aBl + rb + boff);
#pragma unroll
            for (int t = 0; t < 2; t++) {
                mma_bf16(acc[t][2 * bp],     a_hi[t], bh[0], bh[1]);
                mma_bf16(acc[t][2 * bp + 1], a_hi[t], bh[2], bh[3]);
                mma_bf16(acc[t][2 * bp],     a_lo[t], bh[0], bh[1]);
                mma_bf16(acc[t][2 * bp + 1], a_lo[t], bh[2], bh[3]);
                mma_bf16(acc[t][2 * bp],     a_hi[t], blo[0], blo[1]);
                mma_bf16(acc[t][2 * bp + 1], a_hi[t], blo[2], blo[3]);
            }
        }
        __syncthreads();
    }

    // epilogue
#pragma unroll
    for (int t = 0; t < 2; t++) {
#pragma unroll
        for (int j = 0; j < 8; j++) {
            int gc = bn0 + wn * 64 + j * 8 + ((lane & 3) << 1);
            int cc = (gc < 256) ? gc : gc - 256;
            float* base = (gc < 256) ? xl : xr;
            const float* bias = (gc < 256) ? bl : br;
            float b0 = bias[cc], b1 = bias[cc + 1];
#pragma unroll
            for (int h = 0; h < 2; h++) {
                int gm = row0 + wm * 32 + t * 16 + (lane >> 2) + h * 8;
                if (gm < M) {
                    float2 v = make_float2(acc[t][j][2 * h] + b0, acc[t][j][2 * h + 1] + b1);
                    *(float2*)(base + (size_t)gm * 256 + cc) = v;
                }
            }
        }
    }
}

// ---------------- CSR edge pass: one warp per dst node, fully fused ----------------
__global__ __launch_bounds__(256) void edge_csr_kernel(
    const int* __restrict__ rowptr, const int* __restrict__ csrc,
    const float* __restrict__ cea, const float* __restrict__ loopa,
    const float* __restrict__ xl, const float* __restrict__ xr,
    const float* __restrict__ we, const float* __restrict__ att,
    const float* __restrict__ bias, float* __restrict__ out, int N) {
    int lane = threadIdx.x & 31;
    int warp = (blockIdx.x * blockDim.x + threadIdx.x) >> 5;
    int nw = (gridDim.x * blockDim.x) >> 5;
    int c0 = lane << 3;
    float wef[8], attf[8], bf[8];
#pragma unroll
    for (int q = 0; q < 8; q++) {
        wef[q] = we[c0 + q]; attf[q] = att[c0 + q]; bf[q] = bias[c0 + q];
    }

    for (int i = warp; i < N; i += nw) {
        const float* pr = xr + (size_t)i * 256 + c0;
        float4 r0 = *(const float4*)pr;
        float4 r1 = *(const float4*)(pr + 4);
        float rv[8] = {r0.x, r0.y, r0.z, r0.w, r1.x, r1.y, r1.z, r1.w};
        float acc[8] = {0, 0, 0, 0, 0, 0, 0, 0};
        float den = 0.f;

        int rb = rowptr[i], re = rowptr[i + 1];
        float ea = loopa[i];
        const float* pl = xl + (size_t)i * 256 + c0;
        float4 a0 = *(const float4*)pl;
        float4 a1 = *(const float4*)(pl + 4);

        int j = rb;
        while (true) {
            bool has = (j < re);
            float4 b0, b1; float ean = 0.f;
            if (has) {
                int sn = csrc[j];
                ean = cea[j];
                const float* pn = xl + (size_t)sn * 256 + c0;
                b0 = *(const float4*)pn;
                b1 = *(const float4*)(pn + 4);
            }
            float lv[8] = {a0.x, a0.y, a0.z, a0.w, a1.x, a1.y, a1.z, a1.w};
            float a = 0.f;
#pragma unroll
            for (int q = 0; q < 8; q++) {
                float m = lv[q] + rv[q] + ea * wef[q];
                m = (m > 0.f) ? m : 0.2f * m;
                a += m * attf[q];
            }
            a += __shfl_xor_sync(0xffffffffu, a, 1);
            a += __shfl_xor_sync(0xffffffffu, a, 2);
            a += __shfl_xor_sync(0xffffffffu, a, 4);
            float ex = __expf(a);
            den += ex;
#pragma unroll
            for (int q = 0; q < 8; q++) acc[q] += ex * lv[q];
            if (!has) break;
            a0 = b0; a1 = b1; ea = ean; j++;
        }

        float inv = 1.0f / den;
        float o[8];
#pragma unroll
        for (int q = 0; q < 8; q++) o[q] = fmaxf(acc[q] * inv + bf[q], 0.f);
        float* po = out + (size_t)i * 256 + c0;
        *(float4*)(po)     = *(float4*)(o);
        *(float4*)(po + 4) = *(float4*)(o + 4);
    }
}

// ---------------- global mean pool ----------------
__global__ __launch_bounds__(256) void pool_kernel(
    const float* __restrict__ h, const int* __restrict__ batch,
    float* __restrict__ gsum, float* __restrict__ gcnt, int N) {
    __shared__ int sb[256];
    int t = threadIdx.x;
    int start = blockIdx.x * 256;
    int end = min(start + 256, N);
    int n = end - start;
    if (n <= 0) return;
    if (t < n) sb[t] = batch[start + t];
    __syncthreads();
    float acc = 0.f, cnt = 0.f;
    int cur = sb[0];
    for (int i = 0; i < n; i++) {
        int b = sb[i];
        if (b != cur) {
            atomicAdd(gsum + (size_t)cur * 256 + t, acc);
            if (t == 0) atomicAdd(gcnt + cur, cnt);
            acc = 0.f; cnt = 0.f; cur = b;
        }
        acc += h[(size_t)(start + i) * 256 + t];
        cnt += 1.f;
    }
    atomicAdd(gsum + (size_t)cur * 256 + t, acc);
    if (t == 0) atomicAdd(gcnt + cur, cnt);
}

// ---------------- final MLP ----------------
__global__ __launch_bounds__(128) void mlp_kernel(
    const float* __restrict__ gsum, const float* __restrict__ gcnt,
    const float* __restrict__ p1w, const float* __restrict__ p1b,
    const float* __restrict__ lng, const float* __restrict__ lnb,
    const float* __restrict__ p2w, const float* __restrict__ p2b,
    float* __restrict__ out) {
    __shared__ float gs[256];
    __shared__ float zs[128];
    __shared__ float wsum[4], wsum2[4];
    int b = blockIdx.x, t = threadIdx.x;
    float invc = 1.0f / fmaxf(gcnt[b], 1.0f);
    gs[t] = gsum[(size_t)b * 256 + t] * invc;
    gs[t + 128] = gsum[(size_t)b * 256 + 128 + t] * invc;
    __syncthreads();
    float z = p1b[t];
    for (int k = 0; k < 256; k++) z += gs[k] * p1w[(size_t)k * 128 + t];
    float s = z, s2 = z * z;
#pragma unroll
    for (int o = 16; o; o >>= 1) {
        s += __shfl_xor_sync(0xffffffffu, s, o);
        s2 += __shfl_xor_sync(0xffffffffu, s2, o);
    }
    if ((t & 31) == 0) { wsum[t >> 5] = s; wsum2[t >> 5] = s2; }
    __syncthreads();
    s = wsum[0] + wsum[1] + wsum[2] + wsum[3];
    s2 = wsum2[0] + wsum2[1] + wsum2[2] + wsum2[3];
    float mu = s * (1.0f / 128.0f);
    float var = s2 * (1.0f / 128.0f) - mu * mu;
    float zn = (z - mu) * rsqrtf(var + 1e-5f) * lng[t] + lnb[t];
    zs[t] = fmaxf(zn, 0.f);
    __syncthreads();
    if (t < 64) {
        float o = p2b[t];
        for (int j = 0; j < 128; j++) o += zs[j] * p2w[(size_t)j * 64 + t];
        out[(size_t)b * 64 + t] = fmaxf(o, 0.f);
    }
}

extern "C" void kernel_launch(void* const* d_in, const int* in_sizes, int n_in,
                              void* d_out, int out_size) {
    const float* x      = (const float*)d_in[0];
    const int*   ei     = (const int*)d_in[1];
    const float* eattr  = (const float*)d_in[2];
    const int*   batch  = (const int*)d_in[3];
    const float* enc_w  = (const float*)d_in[4];
    const float* enc_b  = (const float*)d_in[5];
    const float* g1_wl  = (const float*)d_in[6];
    const float* g1_bl  = (const float*)d_in[7];
    const float* g1_wr  = (const float*)d_in[8];
    const float* g1_br  = (const float*)d_in[9];
    const float* g1_we  = (const float*)d_in[10];
    const float* g1_att = (const float*)d_in[11];
    const float* g1_bias= (const float*)d_in[12];
    const float* g2_wl  = (const float*)d_in[13];
    const float* g2_bl  = (const float*)d_in[14];
    const float* g2_wr  = (const float*)d_in[15];
    const float* g2_br  = (const float*)d_in[16];
    const float* g2_we  = (const float*)d_in[17];
    const float* g2_att = (const float*)d_in[18];
    const float* g2_bias= (const float*)d_in[19];
    const float* p1_w   = (const float*)d_in[20];
    const float* p1_b   = (const float*)d_in[21];
    const float* ln_g   = (const float*)d_in[22];
    const float* ln_b   = (const float*)d_in[23];
    const float* p2_w   = (const float*)d_in[24];
    const float* p2_b   = (const float*)d_in[25];

    int N = in_sizes[3];
    int E = in_sizes[2];
    int NG_ = out_size / 64;

    float *h64, *xl, *xr, *h1, *h2, *loopsum, *loopa, *cea, *gsum, *gcnt;
    int *cnt, *rowptr, *pos, *csrc;
    unsigned short *ahi, *alo, *w1hi, *w1lo, *w2hi, *w2lo;
    cudaGetSymbolAddress((void**)&h64, d_h64);
    cudaGetSymbolAddress((void**)&xl, d_xl);
    cudaGetSymbolAddress((void**)&xr, d_xr);
    cudaGetSymbolAddress((void**)&h1, d_h1);
    cudaGetSymbolAddress((void**)&h2, d_h2);
    cudaGetSymbolAddress((void**)&cnt, d_cnt);
    cudaGetSymbolAddress((void**)&loopsum, d_loopsum);
    cudaGetSymbolAddress((void**)&loopa, d_loopa);
    cudaGetSymbolAddress((void**)&rowptr, d_rowptr);
    cudaGetSymbolAddress((void**)&pos, d_pos);
    cudaGetSymbolAddress((void**)&csrc, d_csrc);
    cudaGetSymbolAddress((void**)&cea, d_cea);
    cudaGetSymbolAddress((void**)&gsum, d_gsum);
    cudaGetSymbolAddress((void**)&gcnt, d_gcnt);
    cudaGetSymbolAddress((void**)&ahi, d_ahi);
    cudaGetSymbolAddress((void**)&alo, d_alo);
    cudaGetSymbolAddress((void**)&w1hi, d_w1hi);
    cudaGetSymbolAddress((void**)&w1lo, d_w1lo);
    cudaGetSymbolAddress((void**)&w2hi, d_w2hi);
    cudaGetSymbolAddress((void**)&w2lo, d_w2lo);

    int ntiles = (N + 127) / 128;
    int eblocks = (N * 32 + 255) / 256;
    dim3 ggrid(4, ntiles);

    // ---- CSR build + weight conversion ----
    cudaMemsetAsync(cnt, 0, (size_t)N * sizeof(int));
    cudaMemsetAsync(loopsum, 0, (size_t)N * sizeof(float));
    encoder_kernel<<<(N * 64 + 255) / 256, 256>>>(x, enc_w, enc_b, h64, N);
    count_kernel<<<(E + 255) / 256, 256>>>(ei, eattr, cnt, loopsum, E);
    scan_kernel<<<1, 1024>>>(cnt, loopsum, rowptr, pos, loopa, N, E);
    scatter_kernel<<<(E + 255) / 256, 256>>>(ei, eattr, pos, csrc, cea, E);
    conv_w_kernel<<<(512 * 8 + 255) / 256, 256>>>(g1_wl, g1_wr, 64, w1hi, w1lo);
    conv_w_kernel<<<(512 * 32 + 255) / 256, 256>>>(g2_wl, g2_wr, 256, w2hi, w2lo);

    // ---- GAT layer 1 (K = 64) ----
    conv_a_kernel<<<(N * 8 + 255) / 256, 256>>>(h64, N, 64, ahi, alo);
    gemm_mma_kernel<<<ggrid, 256>>>(ahi, alo, w1hi, w1lo, g1_bl, g1_br, xl, xr, N, 64);
    edge_csr_kernel<<<eblocks, 256>>>(rowptr, csrc, cea, loopa, xl, xr,
                                      g1_we, g1_att, g1_bias, h1, N);

    // ---- GAT layer 2 (K = 256) ----
    conv_a_kernel<<<(N * 32 + 255) / 256, 256>>>(h1, N, 256, ahi, alo);
    gemm_mma_kernel<<<ggrid, 256>>>(ahi, alo, w2hi, w2lo, g2_bl, g2_br, xl, xr, N, 256);
    edge_csr_kernel<<<eblocks, 256>>>(rowptr, csrc, cea, loopa, xl, xr,
                                      g2_we, g2_att, g2_bias, h2, N);

    // ---- pool + MLP ----
    cudaMemsetAsync(gsum, 0, (size_t)NG_ * 256 * sizeof(float));
    cudaMemsetAsync(gcnt, 0, (size_t)NG_ * sizeof(float));
    pool_kernel<<<(N + 255) / 256, 256>>>(h2, batch, gsum, gcnt, N);
    mlp_kernel<<<NG_, 128>>>(gsum, gcnt, p1_w, p1_b, ln_g, ln_b, p2_w, p2_b, (float*)d_out);
}

// round 7
// speedup vs baseline: 1.4843x; 1.0428x over previous
#include <cuda_runtime.h>
#include <cuda_bf16.h>
#include <cstdint>

#define MAXN 50000
#define MAXE 800000
#define MAXT 391            // ceil(MAXN/128)

// ---------------- device scratch ----------------
__device__ float d_h64[MAXN * 64];
__device__ float d_xl[MAXN * 256];
__device__ float d_xr[MAXN * 256];
__device__ float d_h1[MAXN * 256];
__device__ float d_h2[MAXN * 256];
__device__ int   d_cnt[MAXN];
__device__ float d_loopsum[MAXN];
__device__ float d_loopa[MAXN];
__device__ int   d_rowptr[MAXN + 1];
__device__ int   d_pos[MAXN];
__device__ int   d_csrc[MAXE];
__device__ float d_cea[MAXE];
__device__ float d_gsum[64 * 256];
__device__ float d_gcnt[64];
// bf16 hi/lo images, padded to full 128-row tiles
__device__ __align__(16) unsigned short d_ahi[MAXT * 128 * 256];
__device__ __align__(16) unsigned short d_alo[MAXT * 128 * 256];
// transposed combined weights Wt[n][k] (n: 0-255 = wl cols, 256-511 = wr cols)
__device__ __align__(16) unsigned short d_w1hi[512 * 64],  d_w1lo[512 * 64];
__device__ __align__(16) unsigned short d_w2hi[512 * 256], d_w2lo[512 * 256];

// ---------------- helpers ----------------
__device__ __forceinline__ uint32_t smem_u32(const void* p) {
    uint32_t a;
    asm("{ .reg .u64 t; cvta.to.shared.u64 t, %1; cvt.u32.u64 %0, t; }" : "=r"(a) : "l"(p));
    return a;
}
__device__ __forceinline__ void ldsm4(uint32_t* r, uint32_t addr) {
    asm volatile("ldmatrix.sync.aligned.m8n8.x4.shared.b16 {%0,%1,%2,%3}, [%4];"
                 : "=r"(r[0]), "=r"(r[1]), "=r"(r[2]), "=r"(r[3]) : "r"(addr));
}
__device__ __forceinline__ void mma_bf16(float* c, const uint32_t* a, uint32_t b0, uint32_t b1) {
    asm volatile("mma.sync.aligned.m16n8k16.row.col.f32.bf16.bf16.f32 "
                 "{%0,%1,%2,%3}, {%4,%5,%6,%7}, {%8,%9}, {%0,%1,%2,%3};"
                 : "+f"(c[0]), "+f"(c[1]), "+f"(c[2]), "+f"(c[3])
                 : "r"(a[0]), "r"(a[1]), "r"(a[2]), "r"(a[3]), "r"(b0), "r"(b1));
}
__device__ __forceinline__ void cp16(uint32_t saddr, const void* gaddr) {
    asm volatile("cp.async.cg.shared.global [%0], [%1], 16;" :: "r"(saddr), "l"(gaddr));
}
__device__ __forceinline__ void cp_commit() {
    asm volatile("cp.async.commit_group;");
}
template <int Nw>
__device__ __forceinline__ void cp_wait() {
    asm volatile("cp.async.wait_group %0;" :: "n"(Nw));
}
__device__ __forceinline__ void split_bf16(float v, unsigned short& h, unsigned short& l) {
    __nv_bfloat16 hb = __float2bfloat16_rn(v);
    float r = v - __bfloat162float(hb);
    __nv_bfloat16 lb = __float2bfloat16_rn(r);
    h = __bfloat16_as_ushort(hb);
    l = __bfloat16_as_ushort(lb);
}

// ---------------- encoder: h = relu(x @ W[4,64] + b) ----------------
__global__ void encoder_kernel(const float* __restrict__ x,
                               const float* __restrict__ w,
                               const float* __restrict__ b,
                               float* __restrict__ h, int N) {
    int idx = blockIdx.x * blockDim.x + threadIdx.x;
    if (idx >= N * 64) return;
    int i = idx >> 6, j = idx & 63;
    float4 xv = *(const float4*)(x + (size_t)i * 4);
    float s = b[j] + xv.x * w[j] + xv.y * w[64 + j] + xv.z * w[128 + j] + xv.w * w[192 + j];
    h[idx] = fmaxf(s, 0.f);
}

// ---------------- CSR build ----------------
__global__ void count_kernel(const int* __restrict__ ei, const float* __restrict__ eattr,
                             int* __restrict__ cnt, float* __restrict__ loopsum, int E) {
    int e = blockIdx.x * blockDim.x + threadIdx.x;
    if (e >= E) return;
    int dst = ei[E + e];
    atomicAdd(cnt + dst, 1);
    atomicAdd(loopsum + dst, eattr[e]);
}

__global__ __launch_bounds__(1024) void scan_kernel(
    const int* __restrict__ cnt, const float* __restrict__ loopsum,
    int* __restrict__ rowptr, int* __restrict__ pos, float* __restrict__ loopa,
    int N, int E) {
    __shared__ int part[1024];
    int t = threadIdx.x;
    int chunk = (N + 1023) / 1024;
    int b0 = t * chunk, b1 = min(b0 + chunk, N);
    int s = 0;
    for (int j = b0; j < b1; j++) s += cnt[j];
    part[t] = s;
    __syncthreads();
    for (int off = 1; off < 1024; off <<= 1) {
        int v = (t >= off) ? part[t - off] : 0;
        __syncthreads();
        part[t] += v;
        __syncthreads();
    }
    int run = (t == 0) ? 0 : part[t - 1];
    for (int j = b0; j < b1; j++) {
        rowptr[j] = run;
        pos[j] = run;
        int c = cnt[j];
        loopa[j] = loopsum[j] / (float)max(c, 1);
        run += c;
    }
    if (t == 1023) rowptr[N] = E;
}

__global__ void scatter_kernel(const int* __restrict__ ei, const float* __restrict__ eattr,
                               int* __restrict__ pos,
                               int* __restrict__ csrc, float* __restrict__ cea, int E) {
    int e = blockIdx.x * blockDim.x + threadIdx.x;
    if (e >= E) return;
    int dst = ei[E + e];
    int p = atomicAdd(pos + dst, 1);
    csrc[p] = ei[e];
    cea[p] = eattr[e];
}

// ---------------- A fp32 [M,K] -> bf16 hi/lo (row-major) ----------------
__global__ void conv_a_kernel(const float* __restrict__ A, int M, int K,
                              unsigned short* __restrict__ hi, unsigned short* __restrict__ lo) {
    int total = M * (K >> 3);
    int gid = blockIdx.x * blockDim.x + threadIdx.x;
    if (gid >= total) return;
    size_t off = (size_t)gid * 8;
    float4 f0 = *(const float4*)(A + off);
    float4 f1 = *(const float4*)(A + off + 4);
    float v[8] = {f0.x, f0.y, f0.z, f0.w, f1.x, f1.y, f1.z, f1.w};
    uint32_t hv[4], lv[4];
#pragma unroll
    for (int q = 0; q < 4; q++) {
        unsigned short h0, l0, h1, l1;
        split_bf16(v[2 * q], h0, l0);
        split_bf16(v[2 * q + 1], h1, l1);
        hv[q] = (uint32_t)h0 | ((uint32_t)h1 << 16);
        lv[q] = (uint32_t)l0 | ((uint32_t)l1 << 16);
    }
    *(uint4*)(hi + off) = make_uint4(hv[0], hv[1], hv[2], hv[3]);
    *(uint4*)(lo + off) = make_uint4(lv[0], lv[1], lv[2], lv[3]);
}

// ---------------- W [K,256] x2 -> combined transposed Wt[n][k] bf16 hi/lo ----------------
__global__ void conv_w_kernel(const float* __restrict__ wl, const float* __restrict__ wr,
                              int K,
                              unsigned short* __restrict__ hi, unsigned short* __restrict__ lo) {
    int gpr = K >> 3;
    int total = 512 * gpr;
    int gid = blockIdx.x * blockDim.x + threadIdx.x;
    if (gid >= total) return;
    int n = gid / gpr, g = gid % gpr;
    int ks = g * 8;
    const float* src = (n < 256) ? wl : wr;
    int col = n & 255;
    uint32_t hv[4], lv[4];
#pragma unroll
    for (int q = 0; q < 4; q++) {
        float v0 = src[(size_t)(ks + 2 * q) * 256 + col];
        float v1 = src[(size_t)(ks + 2 * q + 1) * 256 + col];
        unsigned short h0, l0, h1, l1;
        split_bf16(v0, h0, l0);
        split_bf16(v1, h1, l1);
        hv[q] = (uint32_t)h0 | ((uint32_t)h1 << 16);
        lv[q] = (uint32_t)l0 | ((uint32_t)l1 << 16);
    }
    size_t off = (size_t)n * K + ks;
    *(uint4*)(hi + off) = make_uint4(hv[0], hv[1], hv[2], hv[3]);
    *(uint4*)(lo + off) = make_uint4(lv[0], lv[1], lv[2], lv[3]);
}

// ---------------- mma.sync dual GEMM, cp.async double-buffered ----------------
// C[M,512] = A[M,K] @ Wt^T + bias  (split-bf16: Ahi*Whi + Ahi*Wlo + Alo*Whi)
// cols 0-255 -> xl, 256-511 -> xr. CTA tile 128x128, warp tile 32x64, BK=16.
#define SROW 24   // ushorts per smem row (48B stride, conflict-free for ldmatrix)
__global__ __launch_bounds__(256) void gemm_mma_kernel(
    const unsigned short* __restrict__ ahi, const unsigned short* __restrict__ alo,
    const unsigned short* __restrict__ whi, const unsigned short* __restrict__ wlo,
    const float* __restrict__ bl, const float* __restrict__ br,
    float* __restrict__ xl, float* __restrict__ xr, int M, int K) {
    __shared__ __align__(16) unsigned short sAh[2][128 * SROW], sAl[2][128 * SROW];
    __shared__ __align__(16) unsigned short sBh[2][128 * SROW], sBl[2][128 * SROW];

    int tid = threadIdx.x, lane = tid & 31, wid = tid >> 5;
    int wm = wid & 3, wn = wid >> 2;
    int row0 = blockIdx.y * 128, bn0 = blockIdx.x * 128;

    float acc[2][8][4];
#pragma unroll
    for (int t = 0; t < 2; t++)
#pragma unroll
        for (int j = 0; j < 8; j++)
#pragma unroll
            for (int q = 0; q < 4; q++) acc[t][j][q] = 0.f;

    // staging: thread -> (row = tid/2, khalf = tid%2); uint4 index stride 3/row
    int srow = tid >> 1, kh = (tid & 1) << 3;
    uint32_t soff = (uint32_t)((srow * 3 + (tid & 1)) * 16);
    const int nstage = K >> 4;

    uint32_t bAh[2] = {smem_u32(sAh[0]), smem_u32(sAh[1])};
    uint32_t bAl[2] = {smem_u32(sAl[0]), smem_u32(sAl[1])};
    uint32_t bBh[2] = {smem_u32(sBh[0]), smem_u32(sBh[1])};
    uint32_t bBl[2] = {smem_u32(sBl[0]), smem_u32(sBl[1])};

    // ldmatrix lane addresses
    uint32_t aoff = (uint32_t)((lane & 15) * 48 + ((lane >> 4) << 4));
    uint32_t boff = (uint32_t)((((lane >> 4) << 3) + (lane & 7)) * 48 + (((lane >> 3) & 1) << 4));

    size_t gA = (size_t)(row0 + srow) * K + kh;
    size_t gB = (size_t)(bn0 + srow) * K + kh;

    auto issue = [&](int s, int b) {
        size_t o = (size_t)s * 16;
        cp16(bAh[b] + soff, ahi + gA + o);
        cp16(bAl[b] + soff, alo + gA + o);
        cp16(bBh[b] + soff, whi + gB + o);
        cp16(bBl[b] + soff, wlo + gB + o);
        cp_commit();
    };

    issue(0, 0);

    for (int s = 0; s < nstage; s++) {
        int buf = s & 1;
        if (s + 1 < nstage) {
            issue(s + 1, buf ^ 1);
            cp_wait<1>();
        } else {
            cp_wait<0>();
        }
        __syncthreads();

        uint32_t a_hi[2][4], a_lo[2][4];
#pragma unroll
        for (int t = 0; t < 2; t++) {
            uint32_t ra = (uint32_t)((wm * 32 + t * 16) * 48);
            ldsm4(a_hi[t], bAh[buf] + ra + aoff);
            ldsm4(a_lo[t], bAl[buf] + ra + aoff);
        }
#pragma unroll
        for (int bp = 0; bp < 4; bp++) {
            uint32_t rb = (uint32_t)((wn * 64 + bp * 16) * 48);
            uint32_t bh[4], blo[4];
            ldsm4(bh, bBh[buf] + rb + boff);
            ldsm4(blo, bBl[buf] + rb + boff);
#pragma unroll
            for (int t = 0; t < 2; t++) {
                mma_bf16(acc[t][2 * bp],     a_hi[t], bh[0], bh[1]);
                mma_bf16(acc[t][2 * bp + 1], a_hi[t], bh[2], bh[3]);
                mma_bf16(acc[t][2 * bp],     a_lo[t], bh[0], bh[1]);
                mma_bf16(acc[t][2 * bp + 1], a_lo[t], bh[2], bh[3]);
                mma_bf16(acc[t][2 * bp],     a_hi[t], blo[0], blo[1]);
                mma_bf16(acc[t][2 * bp + 1], a_hi[t], blo[2], blo[3]);
            }
        }
        __syncthreads();
    }

    // epilogue
#pragma unroll
    for (int t = 0; t < 2; t++) {
#pragma unroll
        for (int j = 0; j < 8; j++) {
            int gc = bn0 + wn * 64 + j * 8 + ((lane & 3) << 1);
            int cc = (gc < 256) ? gc : gc - 256;
            float* base = (gc < 256) ? xl : xr;
            const float* bias = (gc < 256) ? bl : br;
            float b0 = bias[cc], b1 = bias[cc + 1];
#pragma unroll
            for (int h = 0; h < 2; h++) {
                int gm = row0 + wm * 32 + t * 16 + (lane >> 2) + h * 8;
                if (gm < M) {
                    float2 v = make_float2(acc[t][j][2 * h] + b0, acc[t][j][2 * h + 1] + b1);
                    *(float2*)(base + (size_t)gm * 256 + cc) = v;
                }
            }
        }
    }
}

// ---------------- CSR edge pass: one warp per dst node, fully fused ----------------
__global__ __launch_bounds__(256) void edge_csr_kernel(
    const int* __restrict__ rowptr, const int* __restrict__ csrc,
    const float* __restrict__ cea, const float* __restrict__ loopa,
    const float* __restrict__ xl, const float* __restrict__ xr,
    const float* __restrict__ we, const float* __restrict__ att,
    const float* __restrict__ bias, float* __restrict__ out, int N) {
    int lane = threadIdx.x & 31;
    int warp = (blockIdx.x * blockDim.x + threadIdx.x) >> 5;
    int nw = (gridDim.x * blockDim.x) >> 5;
    int c0 = lane << 3;
    float wef[8], attf[8], bf[8];
#pragma unroll
    for (int q = 0; q < 8; q++) {
        wef[q] = we[c0 + q]; attf[q] = att[c0 + q]; bf[q] = bias[c0 + q];
    }

    for (int i = warp; i < N; i += nw) {
        const float* pr = xr + (size_t)i * 256 + c0;
        float4 r0 = *(const float4*)pr;
        float4 r1 = *(const float4*)(pr + 4);
        float rv[8] = {r0.x, r0.y, r0.z, r0.w, r1.x, r1.y, r1.z, r1.w};
        float acc[8] = {0, 0, 0, 0, 0, 0, 0, 0};
        float den = 0.f;

        int rb = rowptr[i], re = rowptr[i + 1];
        float ea = loopa[i];
        const float* pl = xl + (size_t)i * 256 + c0;
        float4 a0 = *(const float4*)pl;
        float4 a1 = *(const float4*)(pl + 4);

        int j = rb;
        while (true) {
            bool has = (j < re);
            float4 b0, b1; float ean = 0.f;
            if (has) {
                int sn = csrc[j];
                ean = cea[j];
                const float* pn = xl + (size_t)sn * 256 + c0;
                b0 = *(const float4*)pn;
                b1 = *(const float4*)(pn + 4);
            }
            float lv[8] = {a0.x, a0.y, a0.z, a0.w, a1.x, a1.y, a1.z, a1.w};
            float a = 0.f;
#pragma unroll
            for (int q = 0; q < 8; q++) {
                float m = lv[q] + rv[q] + ea * wef[q];
                m = (m > 0.f) ? m : 0.2f * m;
                a += m * attf[q];
            }
            a += __shfl_xor_sync(0xffffffffu, a, 1);
            a += __shfl_xor_sync(0xffffffffu, a, 2);
            a += __shfl_xor_sync(0xffffffffu, a, 4);
            float ex = __expf(a);
            den += ex;
#pragma unroll
            for (int q = 0; q < 8; q++) acc[q] += ex * lv[q];
            if (!has) break;
            a0 = b0; a1 = b1; ea = ean; j++;
        }

        float inv = 1.0f / den;
        float o[8];
#pragma unroll
        for (int q = 0; q < 8; q++) o[q] = fmaxf(acc[q] * inv + bf[q], 0.f);
        float* po = out + (size_t)i * 256 + c0;
        *(float4*)(po)     = *(float4*)(o);
        *(float4*)(po + 4) = *(float4*)(o + 4);
    }
}

// ---------------- global mean pool ----------------
__global__ __launch_bounds__(256) void pool_kernel(
    const float* __restrict__ h, const int* __restrict__ batch,
    float* __restrict__ gsum, float* __restrict__ gcnt, int N) {
    __shared__ int sb[256];
    int t = threadIdx.x;
    int start = blockIdx.x * 256;
    int end = min(start + 256, N);
    int n = end - start;
    if (n <= 0) return;
    if (t < n) sb[t] = batch[start + t];
    __syncthreads();
    float acc = 0.f, cnt = 0.f;
    int cur = sb[0];
    for (int i = 0; i < n; i++) {
        int b = sb[i];
        if (b != cur) {
            atomicAdd(gsum + (size_t)cur * 256 + t, acc);
            if (t == 0) atomicAdd(gcnt + cur, cnt);
            acc = 0.f; cnt = 0.f; cur = b;
        }
        acc += h[(size_t)(start + i) * 256 + t];
        cnt += 1.f;
    }
    atomicAdd(gsum + (size_t)cur * 256 + t, acc);
    if (t == 0) atomicAdd(gcnt + cur, cnt);
}

// ---------------- final MLP ----------------
__global__ __launch_bounds__(128) void mlp_kernel(
    const float* __restrict__ gsum, const float* __restrict__ gcnt,
    const float* __restrict__ p1w, const float* __restrict__ p1b,
    const float* __restrict__ lng, const float* __restrict__ lnb,
    const float* __restrict__ p2w, const float* __restrict__ p2b,
    float* __restrict__ out) {
    __shared__ float gs[256];
    __shared__ float zs[128];
    __shared__ float wsum[4], wsum2[4];
    int b = blockIdx.x, t = threadIdx.x;
    float invc = 1.0f / fmaxf(gcnt[b], 1.0f);
    gs[t] = gsum[(size_t)b * 256 + t] * invc;
    gs[t + 128] = gsum[(size_t)b * 256 + 128 + t] * invc;
    __syncthreads();
    float z = p1b[t];
    for (int k = 0; k < 256; k++) z += gs[k] * p1w[(size_t)k * 128 + t];
    float s = z, s2 = z * z;
#pragma unroll
    for (int o = 16; o; o >>= 1) {
        s += __shfl_xor_sync(0xffffffffu, s, o);
        s2 += __shfl_xor_sync(0xffffffffu, s2, o);
    }
    if ((t & 31) == 0) { wsum[t >> 5] = s; wsum2[t >> 5] = s2; }
    __syncthreads();
    s = wsum[0] + wsum[1] + wsum[2] + wsum[3];
    s2 = wsum2[0] + wsum2[1] + wsum2[2] + wsum2[3];
    float mu = s * (1.0f / 128.0f);
    float var = s2 * (1.0f / 128.0f) - mu * mu;
    float zn = (z - mu) * rsqrtf(var + 1e-5f) * lng[t] + lnb[t];
    zs[t] = fmaxf(zn, 0.f);
    __syncthreads();
    if (t < 64) {
        float o = p2b[t];
        for (int j = 0; j < 128; j++) o += zs[j] * p2w[(size_t)j * 64 + t];
        out[(size_t)b * 64 + t] = fmaxf(o, 0.f);
    }
}

extern "C" void kernel_launch(void* const* d_in, const int* in_sizes, int n_in,
                              void* d_out, int out_size) {
    const float* x      = (const float*)d_in[0];
    const int*   ei     = (const int*)d_in[1];
    const float* eattr  = (const float*)d_in[2];
    const int*   batch  = (const int*)d_in[3];
    const float* enc_w  = (const float*)d_in[4];
    const float* enc_b  = (const float*)d_in[5];
    const float* g1_wl  = (const float*)d_in[6];
    const float* g1_bl  = (const float*)d_in[7];
    const float* g1_wr  = (const float*)d_in[8];
    const float* g1_br  = (const float*)d_in[9];
    const float* g1_we  = (const float*)d_in[10];
    const float* g1_att = (const float*)d_in[11];
    const float* g1_bias= (const float*)d_in[12];
    const float* g2_wl  = (const float*)d_in[13];
    const float* g2_bl  = (const float*)d_in[14];
    const float* g2_wr  = (const float*)d_in[15];
    const float* g2_br  = (const float*)d_in[16];
    const float* g2_we  = (const float*)d_in[17];
    const float* g2_att = (const float*)d_in[18];
    const float* g2_bias= (const float*)d_in[19];
    const float* p1_w   = (const float*)d_in[20];
    const float* p1_b   = (const float*)d_in[21];
    const float* ln_g   = (const float*)d_in[22];
    const float* ln_b   = (const float*)d_in[23];
    const float* p2_w   = (const float*)d_in[24];
    const float* p2_b   = (const float*)d_in[25];

    int N = in_sizes[3];
    int E = in_sizes[2];
    int NG_ = out_size / 64;

    float *h64, *xl, *xr, *h1, *h2, *loopsum, *loopa, *cea, *gsum, *gcnt;
    int *cnt, *rowptr, *pos, *csrc;
    unsigned short *ahi, *alo, *w1hi, *w1lo, *w2hi, *w2lo;
    cudaGetSymbolAddress((void**)&h64, d_h64);
    cudaGetSymbolAddress((void**)&xl, d_xl);
    cudaGetSymbolAddress((void**)&xr, d_xr);
    cudaGetSymbolAddress((void**)&h1, d_h1);
    cudaGetSymbolAddress((void**)&h2, d_h2);
    cudaGetSymbolAddress((void**)&cnt, d_cnt);
    cudaGetSymbolAddress((void**)&loopsum, d_loopsum);
    cudaGetSymbolAddress((void**)&loopa, d_loopa);
    cudaGetSymbolAddress((void**)&rowptr, d_rowptr);
    cudaGetSymbolAddress((void**)&pos, d_pos);
    cudaGetSymbolAddress((void**)&csrc, d_csrc);
    cudaGetSymbolAddress((void**)&cea, d_cea);
    cudaGetSymbolAddress((void**)&gsum, d_gsum);
    cudaGetSymbolAddress((void**)&gcnt, d_gcnt);
    cudaGetSymbolAddress((void**)&ahi, d_ahi);
    cudaGetSymbolAddress((void**)&alo, d_alo);
    cudaGetSymbolAddress((void**)&w1hi, d_w1hi);
    cudaGetSymbolAddress((void**)&w1lo, d_w1lo);
    cudaGetSymbolAddress((void**)&w2hi, d_w2hi);
    cudaGetSymbolAddress((void**)&w2lo, d_w2lo);

    int ntiles = (N + 127) / 128;
    int eblocks = (N * 32 + 255) / 256;
    dim3 ggrid(4, ntiles);

    // Launch order puts the K=64 gemm_mma_kernel at index 5 (ncu captures -s 5 -c 1).
    cudaMemsetAsync(cnt, 0, (size_t)N * sizeof(int));                           // 0
    cudaMemsetAsync(loopsum, 0, (size_t)N * sizeof(float));                     // 1
    encoder_kernel<<<(N * 64 + 255) / 256, 256>>>(x, enc_w, enc_b, h64, N);     // 2
    conv_w_kernel<<<(512 * 8 + 255) / 256, 256>>>(g1_wl, g1_wr, 64, w1hi, w1lo);// 3
    conv_a_kernel<<<(N * 8 + 255) / 256, 256>>>(h64, N, 64, ahi, alo);          // 4
    gemm_mma_kernel<<<ggrid, 256>>>(ahi, alo, w1hi, w1lo, g1_bl, g1_br, xl, xr, N, 64); // 5 <- profiled

    // CSR build (independent of GEMM chain)
    count_kernel<<<(E + 255) / 256, 256>>>(ei, eattr, cnt, loopsum, E);
    scan_kernel<<<1, 1024>>>(cnt, loopsum, rowptr, pos, loopa, N, E);
    scatter_kernel<<<(E + 255) / 256, 256>>>(ei, eattr, pos, csrc, cea, E);

    edge_csr_kernel<<<eblocks, 256>>>(rowptr, csrc, cea, loopa, xl, xr,
                                      g1_we, g1_att, g1_bias, h1, N);

    // ---- GAT layer 2 (K = 256) ----
    conv_w_kernel<<<(512 * 32 + 255) / 256, 256>>>(g2_wl, g2_wr, 256, w2hi, w2lo);
    conv_a_kernel<<<(N * 32 + 255) / 256, 256>>>(h1, N, 256, ahi, alo);
    gemm_mma_kernel<<<ggrid, 256>>>(ahi, alo, w2hi, w2lo, g2_bl, g2_br, xl, xr, N, 256);
    edge_csr_kernel<<<eblocks, 256>>>(rowptr, csrc, cea, loopa, xl, xr,
                                      g2_we, g2_att, g2_bias, h2, N);

    // ---- pool + MLP ----
    cudaMemsetAsync(gsum, 0, (size_t)NG_ * 256 * sizeof(float));
    cudaMemsetAsync(gcnt, 0, (size_t)NG_ * sizeof(float));
    pool_kernel<<<(N + 255) / 256, 256>>>(h2, batch, gsum, gcnt, N);
    mlp_kernel<<<NG_, 128>>>(gsum, gcnt, p1_w, p1_b, ln_g, ln_b, p2_w, p2_b, (float*)d_out);
}

// round 8
// speedup vs baseline: 1.5361x; 1.0349x over previous
#include <cuda_runtime.h>
#include <cuda_bf16.h>
#include <cstdint>

#define MAXN 50000
#define MAXE 800000
#define MAXT 391            // ceil(MAXN/128)

// ---------------- device scratch ----------------
__device__ float d_h64[MAXN * 64];
__device__ float d_xl[MAXN * 256];
__device__ float d_xr[MAXN * 256];
__device__ float d_h1[MAXN * 256];
__device__ float d_h2[MAXN * 256];
__device__ int   d_cnt[MAXN];
__device__ float d_loopsum[MAXN];
__device__ float d_loopa[MAXN];
__device__ int   d_rowptr[MAXN + 1];
__device__ int   d_pos[MAXN];
__device__ int   d_csrc[MAXE];
__device__ float d_cea[MAXE];
__device__ float d_gsum[64 * 256];
__device__ float d_gcnt[64];
// bf16 hi/lo images, padded to full 128-row tiles
__device__ __align__(16) unsigned short d_ahi[MAXT * 128 * 256];
__device__ __align__(16) unsigned short d_alo[MAXT * 128 * 256];
// transposed combined weights Wt[n][k] (n: 0-255 = wl cols, 256-511 = wr cols)
__device__ __align__(16) unsigned short d_w1hi[512 * 64],  d_w1lo[512 * 64];
__device__ __align__(16) unsigned short d_w2hi[512 * 256], d_w2lo[512 * 256];

// ---------------- helpers ----------------
__device__ __forceinline__ uint32_t smem_u32(const void* p) {
    uint32_t a;
    asm("{ .reg .u64 t; cvta.to.shared.u64 t, %1; cvt.u32.u64 %0, t; }" : "=r"(a) : "l"(p));
    return a;
}
__device__ __forceinline__ void ldsm4(uint32_t* r, uint32_t addr) {
    asm volatile("ldmatrix.sync.aligned.m8n8.x4.shared.b16 {%0,%1,%2,%3}, [%4];"
                 : "=r"(r[0]), "=r"(r[1]), "=r"(r[2]), "=r"(r[3]) : "r"(addr));
}
__device__ __forceinline__ void mma_bf16(float* c, const uint32_t* a, uint32_t b0, uint32_t b1) {
    asm volatile("mma.sync.aligned.m16n8k16.row.col.f32.bf16.bf16.f32 "
                 "{%0,%1,%2,%3}, {%4,%5,%6,%7}, {%8,%9}, {%0,%1,%2,%3};"
                 : "+f"(c[0]), "+f"(c[1]), "+f"(c[2]), "+f"(c[3])
                 : "r"(a[0]), "r"(a[1]), "r"(a[2]), "r"(a[3]), "r"(b0), "r"(b1));
}
__device__ __forceinline__ void cp16(uint32_t saddr, const void* gaddr) {
    asm volatile("cp.async.cg.shared.global [%0], [%1], 16;" :: "r"(saddr), "l"(gaddr));
}
__device__ __forceinline__ void cp_commit() {
    asm volatile("cp.async.commit_group;");
}
template <int Nw>
__device__ __forceinline__ void cp_wait() {
    asm volatile("cp.async.wait_group %0;" :: "n"(Nw));
}
__device__ __forceinline__ void split_bf16(float v, unsigned short& h, unsigned short& l) {
    __nv_bfloat16 hb = __float2bfloat16_rn(v);
    float r = v - __bfloat162float(hb);
    __nv_bfloat16 lb = __float2bfloat16_rn(r);
    h = __bfloat16_as_ushort(hb);
    l = __bfloat16_as_ushort(lb);
}

// ---------------- encoder: h = relu(x @ W[4,64] + b) ----------------
__global__ void encoder_kernel(const float* __restrict__ x,
                               const float* __restrict__ w,
                               const float* __restrict__ b,
                               float* __restrict__ h, int N) {
    int idx = blockIdx.x * blockDim.x + threadIdx.x;
    if (idx >= N * 64) return;
    int i = idx >> 6, j = idx & 63;
    float4 xv = *(const float4*)(x + (size_t)i * 4);
    float s = b[j] + xv.x * w[j] + xv.y * w[64 + j] + xv.z * w[128 + j] + xv.w * w[192 + j];
    h[idx] = fmaxf(s, 0.f);
}

// ---------------- CSR build ----------------
__global__ void count_kernel(const int* __restrict__ ei, const float* __restrict__ eattr,
                             int* __restrict__ cnt, float* __restrict__ loopsum, int E) {
    int e = blockIdx.x * blockDim.x + threadIdx.x;
    if (e >= E) return;
    int dst = ei[E + e];
    atomicAdd(cnt + dst, 1);
    atomicAdd(loopsum + dst, eattr[e]);
}

__global__ __launch_bounds__(1024) void scan_kernel(
    const int* __restrict__ cnt, const float* __restrict__ loopsum,
    int* __restrict__ rowptr, int* __restrict__ pos, float* __restrict__ loopa,
    int N, int E) {
    __shared__ int part[1024];
    int t = threadIdx.x;
    int chunk = (N + 1023) / 1024;
    int b0 = t * chunk, b1 = min(b0 + chunk, N);
    int s = 0;
    for (int j = b0; j < b1; j++) s += cnt[j];
    part[t] = s;
    __syncthreads();
    for (int off = 1; off < 1024; off <<= 1) {
        int v = (t >= off) ? part[t - off] : 0;
        __syncthreads();
        part[t] += v;
        __syncthreads();
    }
    int run = (t == 0) ? 0 : part[t - 1];
    for (int j = b0; j < b1; j++) {
        rowptr[j] = run;
        pos[j] = run;
        int c = cnt[j];
        loopa[j] = loopsum[j] / (float)max(c, 1);
        run += c;
    }
    if (t == 1023) rowptr[N] = E;
}

__global__ void scatter_kernel(const int* __restrict__ ei, const float* __restrict__ eattr,
                               int* __restrict__ pos,
                               int* __restrict__ csrc, float* __restrict__ cea, int E) {
    int e = blockIdx.x * blockDim.x + threadIdx.x;
    if (e >= E) return;
    int dst = ei[E + e];
    int p = atomicAdd(pos + dst, 1);
    csrc[p] = ei[e];
    cea[p] = eattr[e];
}

// ---------------- A fp32 [M,K] -> bf16 hi/lo (row-major) ----------------
__global__ void conv_a_kernel(const float* __restrict__ A, int M, int K,
                              unsigned short* __restrict__ hi, unsigned short* __restrict__ lo) {
    int total = M * (K >> 3);
    int gid = blockIdx.x * blockDim.x + threadIdx.x;
    if (gid >= total) return;
    size_t off = (size_t)gid * 8;
    float4 f0 = *(const float4*)(A + off);
    float4 f1 = *(const float4*)(A + off + 4);
    float v[8] = {f0.x, f0.y, f0.z, f0.w, f1.x, f1.y, f1.z, f1.w};
    uint32_t hv[4], lv[4];
#pragma unroll
    for (int q = 0; q < 4; q++) {
        unsigned short h0, l0, h1, l1;
        split_bf16(v[2 * q], h0, l0);
        split_bf16(v[2 * q + 1], h1, l1);
        hv[q] = (uint32_t)h0 | ((uint32_t)h1 << 16);
        lv[q] = (uint32_t)l0 | ((uint32_t)l1 << 16);
    }
    *(uint4*)(hi + off) = make_uint4(hv[0], hv[1], hv[2], hv[3]);
    *(uint4*)(lo + off) = make_uint4(lv[0], lv[1], lv[2], lv[3]);
}

// ---------------- W [K,256] x2 -> combined transposed Wt[n][k] bf16 hi/lo ----------------
__global__ void conv_w_kernel(const float* __restrict__ wl, const float* __restrict__ wr,
                              int K,
                              unsigned short* __restrict__ hi, unsigned short* __restrict__ lo) {
    int gpr = K >> 3;
    int total = 512 * gpr;
    int gid = blockIdx.x * blockDim.x + threadIdx.x;
    if (gid >= total) return;
    int n = gid / gpr, g = gid % gpr;
    int ks = g * 8;
    const float* src = (n < 256) ? wl : wr;
    int col = n & 255;
    uint32_t hv[4], lv[4];
#pragma unroll
    for (int q = 0; q < 4; q++) {
        float v0 = src[(size_t)(ks + 2 * q) * 256 + col];
        float v1 = src[(size_t)(ks + 2 * q + 1) * 256 + col];
        unsigned short h0, l0, h1, l1;
        split_bf16(v0, h0, l0);
        split_bf16(v1, h1, l1);
        hv[q] = (uint32_t)h0 | ((uint32_t)h1 << 16);
        lv[q] = (uint32_t)l0 | ((uint32_t)l1 << 16);
    }
    size_t off = (size_t)n * K + ks;
    *(uint4*)(hi + off) = make_uint4(hv[0], hv[1], hv[2], hv[3]);
    *(uint4*)(lo + off) = make_uint4(lv[0], lv[1], lv[2], lv[3]);
}

// ---------------- mma.sync dual GEMM, cp.async double-buffered, 2 CTA/SM ----------------
#define SROW 24   // ushorts per smem row (48B stride, conflict-free for ldmatrix)
__global__ __launch_bounds__(256, 2) void gemm_mma_kernel(
    const unsigned short* __restrict__ ahi, const unsigned short* __restrict__ alo,
    const unsigned short* __restrict__ whi, const unsigned short* __restrict__ wlo,
    const float* __restrict__ bl, const float* __restrict__ br,
    float* __restrict__ xl, float* __restrict__ xr, int M, int K) {
    __shared__ __align__(16) unsigned short sAh[2][128 * SROW], sAl[2][128 * SROW];
    __shared__ __align__(16) unsigned short sBh[2][128 * SROW], sBl[2][128 * SROW];

    int tid = threadIdx.x, lane = tid & 31, wid = tid >> 5;
    int wm = wid & 3, wn = wid >> 2;
    int row0 = blockIdx.y * 128, bn0 = blockIdx.x * 128;

    float acc[2][8][4];
#pragma unroll
    for (int t = 0; t < 2; t++)
#pragma unroll
        for (int j = 0; j < 8; j++)
#pragma unroll
            for (int q = 0; q < 4; q++) acc[t][j][q] = 0.f;

    int srow = tid >> 1, kh = (tid & 1) << 3;
    uint32_t soff = (uint32_t)((srow * 3 + (tid & 1)) * 16);
    const int nstage = K >> 4;

    uint32_t bAh[2] = {smem_u32(sAh[0]), smem_u32(sAh[1])};
    uint32_t bAl[2] = {smem_u32(sAl[0]), smem_u32(sAl[1])};
    uint32_t bBh[2] = {smem_u32(sBh[0]), smem_u32(sBh[1])};
    uint32_t bBl[2] = {smem_u32(sBl[0]), smem_u32(sBl[1])};

    uint32_t aoff = (uint32_t)((lane & 15) * 48 + ((lane >> 4) << 4));
    uint32_t boff = (uint32_t)((((lane >> 4) << 3) + (lane & 7)) * 48 + (((lane >> 3) & 1) << 4));

    size_t gA = (size_t)(row0 + srow) * K + kh;
    size_t gB = (size_t)(bn0 + srow) * K + kh;

    auto issue = [&](int s, int b) {
        size_t o = (size_t)s * 16;
        cp16(bAh[b] + soff, ahi + gA + o);
        cp16(bAl[b] + soff, alo + gA + o);
        cp16(bBh[b] + soff, whi + gB + o);
        cp16(bBl[b] + soff, wlo + gB + o);
        cp_commit();
    };

    issue(0, 0);

    for (int s = 0; s < nstage; s++) {
        int buf = s & 1;
        if (s + 1 < nstage) {
            issue(s + 1, buf ^ 1);
            cp_wait<1>();
        } else {
            cp_wait<0>();
        }
        __syncthreads();

        uint32_t a_hi[2][4], a_lo[2][4];
#pragma unroll
        for (int t = 0; t < 2; t++) {
            uint32_t ra = (uint32_t)((wm * 32 + t * 16) * 48);
            ldsm4(a_hi[t], bAh[buf] + ra + aoff);
            ldsm4(a_lo[t], bAl[buf] + ra + aoff);
        }
#pragma unroll
        for (int bp = 0; bp < 4; bp++) {
            uint32_t rb = (uint32_t)((wn * 64 + bp * 16) * 48);
            uint32_t bh[4], blo[4];
            ldsm4(bh, bBh[buf] + rb + boff);
            ldsm4(blo, bBl[buf] + rb + boff);
#pragma unroll
            for (int t = 0; t < 2; t++) {
                mma_bf16(acc[t][2 * bp],     a_hi[t], bh[0], bh[1]);
                mma_bf16(acc[t][2 * bp + 1], a_hi[t], bh[2], bh[3]);
                mma_bf16(acc[t][2 * bp],     a_lo[t], bh[0], bh[1]);
                mma_bf16(acc[t][2 * bp + 1], a_lo[t], bh[2], bh[3]);
                mma_bf16(acc[t][2 * bp],     a_hi[t], blo[0], blo[1]);
                mma_bf16(acc[t][2 * bp + 1], a_hi[t], blo[2], blo[3]);
            }
        }
        __syncthreads();
    }

    // epilogue
#pragma unroll
    for (int t = 0; t < 2; t++) {
#pragma unroll
        for (int j = 0; j < 8; j++) {
            int gc = bn0 + wn * 64 + j * 8 + ((lane & 3) << 1);
            int cc = (gc < 256) ? gc : gc - 256;
            float* base = (gc < 256) ? xl : xr;
            const float* bias = (gc < 256) ? bl : br;
            float b0 = bias[cc], b1 = bias[cc + 1];
#pragma unroll
            for (int h = 0; h < 2; h++) {
                int gm = row0 + wm * 32 + t * 16 + (lane >> 2) + h * 8;
                if (gm < M) {
                    float2 v = make_float2(acc[t][j][2 * h] + b0, acc[t][j][2 * h + 1] + b1);
                    *(float2*)(base + (size_t)gm * 256 + cc) = v;
                }
            }
        }
    }
}

// ---------------- CSR edge pass: one warp per dst node, depth-2 x unroll-2 pipeline ----------------
__global__ __launch_bounds__(256) void edge_csr_kernel(
    const int* __restrict__ rowptr, const int* __restrict__ csrc,
    const float* __restrict__ cea, const float* __restrict__ loopa,
    const float* __restrict__ xl, const float* __restrict__ xr,
    const float* __restrict__ we, const float* __restrict__ att,
    const float* __restrict__ bias, float* __restrict__ out, int N) {
    int lane = threadIdx.x & 31;
    int warp = (blockIdx.x * blockDim.x + threadIdx.x) >> 5;
    int nw = (gridDim.x * blockDim.x) >> 5;
    int c0 = lane << 3;
    float wef[8], attf[8], bf[8];
#pragma unroll
    for (int q = 0; q < 8; q++) {
        wef[q] = we[c0 + q]; attf[q] = att[c0 + q]; bf[q] = bias[c0 + q];
    }

    for (int i = warp; i < N; i += nw) {
        const float* pr = xr + (size_t)i * 256 + c0;
        float4 r0 = *(const float4*)pr;
        float4 r1 = *(const float4*)(pr + 4);
        float rv[8] = {r0.x, r0.y, r0.z, r0.w, r1.x, r1.y, r1.z, r1.w};
        float acc[8] = {0, 0, 0, 0, 0, 0, 0, 0};
        float den = 0.f;

        int rb = rowptr[i];
        int deg = rowptr[i + 1] - rb;
        int total = deg + 1;              // + self loop (appended as edge index 'deg')
        float la = loopa[i];

        float4 A0, A1, B0, B1;
        float eA = 0.f, eB = 0.f;

        // prologue: load edges 0 and 1
        {
            int s = (0 < deg) ? __ldg(csrc + rb) : i;
            eA = (0 < deg) ? __ldg(cea + rb) : la;
            const float* p = xl + (size_t)s * 256 + c0;
            A0 = *(const float4*)p; A1 = *(const float4*)(p + 4);
        }
        if (total > 1) {
            int s = (1 < deg) ? __ldg(csrc + rb + 1) : i;
            eB = (1 < deg) ? __ldg(cea + rb + 1) : la;
            const float* p = xl + (size_t)s * 256 + c0;
            B0 = *(const float4*)p; B1 = *(const float4*)(p + 4);
        }

        for (int k = 0; k < total; k += 2) {
            float4 C0, C1, D0, D1;
            float eC = 0.f, eD = 0.f;
            if (k + 2 < total) {
                int s = (k + 2 < deg) ? __ldg(csrc + rb + k + 2) : i;
                eC = (k + 2 < deg) ? __ldg(cea + rb + k + 2) : la;
                const float* p = xl + (size_t)s * 256 + c0;
                C0 = *(const float4*)p; C1 = *(const float4*)(p + 4);
            }
            if (k + 3 < total) {
                int s = (k + 3 < deg) ? __ldg(csrc + rb + k + 3) : i;
                eD = (k + 3 < deg) ? __ldg(cea + rb + k + 3) : la;
                const float* p = xl + (size_t)s * 256 + c0;
                D0 = *(const float4*)p; D1 = *(const float4*)(p + 4);
            }
            // compute edge k
            {
                float lv[8] = {A0.x, A0.y, A0.z, A0.w, A1.x, A1.y, A1.z, A1.w};
                float a = 0.f;
#pragma unroll
                for (int q = 0; q < 8; q++) {
                    float m = lv[q] + rv[q] + eA * wef[q];
                    m = (m > 0.f) ? m : 0.2f * m;
                    a += m * attf[q];
                }
                a += __shfl_xor_sync(0xffffffffu, a, 1);
                a += __shfl_xor_sync(0xffffffffu, a, 2);
                a += __shfl_xor_sync(0xffffffffu, a, 4);
                float ex = __expf(a);
                den += ex;
#pragma unroll
                for (int q = 0; q < 8; q++) acc[q] += ex * lv[q];
            }
            // compute edge k+1
            if (k + 1 < total) {
                float lv[8] = {B0.x, B0.y, B0.z, B0.w, B1.x, B1.y, B1.z, B1.w};
                float a = 0.f;
#pragma unroll
                for (int q = 0; q < 8; q++) {
                    float m = lv[q] + rv[q] + eB * wef[q];
                    m = (m > 0.f) ? m : 0.2f * m;
                    a += m * attf[q];
                }
                a += __shfl_xor_sync(0xffffffffu, a, 1);
                a += __shfl_xor_sync(0xffffffffu, a, 2);
                a += __shfl_xor_sync(0xffffffffu, a, 4);
                float ex = __expf(a);
                den += ex;
#pragma unroll
                for (int q = 0; q < 8; q++) acc[q] += ex * lv[q];
            }
            A0 = C0; A1 = C1; eA = eC;
            B0 = D0; B1 = D1; eB = eD;
        }

        float inv = 1.0f / den;
        float o[8];
#pragma unroll
        for (int q = 0; q < 8; q++) o[q] = fmaxf(acc[q] * inv + bf[q], 0.f);
        float* po = out + (size_t)i * 256 + c0;
        *(float4*)(po)     = *(float4*)(o);
        *(float4*)(po + 4) = *(float4*)(o + 4);
    }
}

// ---------------- global mean pool ----------------
__global__ __launch_bounds__(256) void pool_kernel(
    const float* __restrict__ h, const int* __restrict__ batch,
    float* __restrict__ gsum, float* __restrict__ gcnt, int N) {
    __shared__ int sb[256];
    int t = threadIdx.x;
    int start = blockIdx.x * 256;
    int end = min(start + 256, N);
    int n = end - start;
    if (n <= 0) return;
    if (t < n) sb[t] = batch[start + t];
    __syncthreads();
    float acc = 0.f, cnt = 0.f;
    int cur = sb[0];
    for (int i = 0; i < n; i++) {
        int b = sb[i];
        if (b != cur) {
            atomicAdd(gsum + (size_t)cur * 256 + t, acc);
            if (t == 0) atomicAdd(gcnt + cur, cnt);
            acc = 0.f; cnt = 0.f; cur = b;
        }
        acc += h[(size_t)(start + i) * 256 + t];
        cnt += 1.f;
    }
    atomicAdd(gsum + (size_t)cur * 256 + t, acc);
    if (t == 0) atomicAdd(gcnt + cur, cnt);
}

// ---------------- final MLP ----------------
__global__ __launch_bounds__(128) void mlp_kernel(
    const float* __restrict__ gsum, const float* __restrict__ gcnt,
    const float* __restrict__ p1w, const float* __restrict__ p1b,
    const float* __restrict__ lng, const float* __restrict__ lnb,
    const float* __restrict__ p2w, const float* __restrict__ p2b,
    float* __restrict__ out) {
    __shared__ float gs[256];
    __shared__ float zs[128];
    __shared__ float wsum[4], wsum2[4];
    int b = blockIdx.x, t = threadIdx.x;
    float invc = 1.0f / fmaxf(gcnt[b], 1.0f);
    gs[t] = gsum[(size_t)b * 256 + t] * invc;
    gs[t + 128] = gsum[(size_t)b * 256 + 128 + t] * invc;
    __syncthreads();
    float z = p1b[t];
    for (int k = 0; k < 256; k++) z += gs[k] * p1w[(size_t)k * 128 + t];
    float s = z, s2 = z * z;
#pragma unroll
    for (int o = 16; o; o >>= 1) {
        s += __shfl_xor_sync(0xffffffffu, s, o);
        s2 += __shfl_xor_sync(0xffffffffu, s2, o);
    }
    if ((t & 31) == 0) { wsum[t >> 5] = s; wsum2[t >> 5] = s2; }
    __syncthreads();
    s = wsum[0] + wsum[1] + wsum[2] + wsum[3];
    s2 = wsum2[0] + wsum2[1] + wsum2[2] + wsum2[3];
    float mu = s * (1.0f / 128.0f);
    float var = s2 * (1.0f / 128.0f) - mu * mu;
    float zn = (z - mu) * rsqrtf(var + 1e-5f) * lng[t] + lnb[t];
    zs[t] = fmaxf(zn, 0.f);
    __syncthreads();
    if (t < 64) {
        float o = p2b[t];
        for (int j = 0; j < 128; j++) o += zs[j] * p2w[(size_t)j * 64 + t];
        out[(size_t)b * 64 + t] = fmaxf(o, 0.f);
    }
}

extern "C" void kernel_launch(void* const* d_in, const int* in_sizes, int n_in,
                              void* d_out, int out_size) {
    const float* x      = (const float*)d_in[0];
    const int*   ei     = (const int*)d_in[1];
    const float* eattr  = (const float*)d_in[2];
    const int*   batch  = (const int*)d_in[3];
    const float* enc_w  = (const float*)d_in[4];
    const float* enc_b  = (const float*)d_in[5];
    const float* g1_wl  = (const float*)d_in[6];
    const float* g1_bl  = (const float*)d_in[7];
    const float* g1_wr  = (const float*)d_in[8];
    const float* g1_br  = (const float*)d_in[9];
    const float* g1_we  = (const float*)d_in[10];
    const float* g1_att = (const float*)d_in[11];
    const float* g1_bias= (const float*)d_in[12];
    const float* g2_wl  = (const float*)d_in[13];
    const float* g2_bl  = (const float*)d_in[14];
    const float* g2_wr  = (const float*)d_in[15];
    const float* g2_br  = (const float*)d_in[16];
    const float* g2_we  = (const float*)d_in[17];
    const float* g2_att = (const float*)d_in[18];
    const float* g2_bias= (const float*)d_in[19];
    const float* p1_w   = (const float*)d_in[20];
    const float* p1_b   = (const float*)d_in[21];
    const float* ln_g   = (const float*)d_in[22];
    const float* ln_b   = (const float*)d_in[23];
    const float* p2_w   = (const float*)d_in[24];
    const float* p2_b   = (const float*)d_in[25];

    int N = in_sizes[3];
    int E = in_sizes[2];
    int NG_ = out_size / 64;

    float *h64, *xl, *xr, *h1, *h2, *loopsum, *loopa, *cea, *gsum, *gcnt;
    int *cnt, *rowptr, *pos, *csrc;
    unsigned short *ahi, *alo, *w1hi, *w1lo, *w2hi, *w2lo;
    cudaGetSymbolAddress((void**)&h64, d_h64);
    cudaGetSymbolAddress((void**)&xl, d_xl);
    cudaGetSymbolAddress((void**)&xr, d_xr);
    cudaGetSymbolAddress((void**)&h1, d_h1);
    cudaGetSymbolAddress((void**)&h2, d_h2);
    cudaGetSymbolAddress((void**)&cnt, d_cnt);
    cudaGetSymbolAddress((void**)&loopsum, d_loopsum);
    cudaGetSymbolAddress((void**)&loopa, d_loopa);
    cudaGetSymbolAddress((void**)&rowptr, d_rowptr);
    cudaGetSymbolAddress((void**)&pos, d_pos);
    cudaGetSymbolAddress((void**)&csrc, d_csrc);
    cudaGetSymbolAddress((void**)&cea, d_cea);
    cudaGetSymbolAddress((void**)&gsum, d_gsum);
    cudaGetSymbolAddress((void**)&gcnt, d_gcnt);
    cudaGetSymbolAddress((void**)&ahi, d_ahi);
    cudaGetSymbolAddress((void**)&alo, d_alo);
    cudaGetSymbolAddress((void**)&w1hi, d_w1hi);
    cudaGetSymbolAddress((void**)&w1lo, d_w1lo);
    cudaGetSymbolAddress((void**)&w2hi, d_w2hi);
    cudaGetSymbolAddress((void**)&w2lo, d_w2lo);

    int ntiles = (N + 127) / 128;
    int eblocks = (N * 32 + 255) / 256;
    dim3 ggrid(4, ntiles);

    // Launch order keeps the K=64 gemm_mma_kernel at index 5 (ncu captures -s 5 -c 1).
    cudaMemsetAsync(cnt, 0, (size_t)N * sizeof(int));                           // 0
    cudaMemsetAsync(loopsum, 0, (size_t)N * sizeof(float));                     // 1
    encoder_kernel<<<(N * 64 + 255) / 256, 256>>>(x, enc_w, enc_b, h64, N);     // 2
    conv_w_kernel<<<(512 * 8 + 255) / 256, 256>>>(g1_wl, g1_wr, 64, w1hi, w1lo);// 3
    conv_a_kernel<<<(N * 8 + 255) / 256, 256>>>(h64, N, 64, ahi, alo);          // 4
    gemm_mma_kernel<<<ggrid, 256>>>(ahi, alo, w1hi, w1lo, g1_bl, g1_br, xl, xr, N, 64); // 5 <- profiled

    // CSR build (independent of GEMM chain)
    count_kernel<<<(E + 255) / 256, 256>>>(ei, eattr, cnt, loopsum, E);
    scan_kernel<<<1, 1024>>>(cnt, loopsum, rowptr, pos, loopa, N, E);
    scatter_kernel<<<(E + 255) / 256, 256>>>(ei, eattr, pos, csrc, cea, E);

    edge_csr_kernel<<<eblocks, 256>>>(rowptr, csrc, cea, loopa, xl, xr,
                                      g1_we, g1_att, g1_bias, h1, N);

    // ---- GAT layer 2 (K = 256) ----
    conv_w_kernel<<<(512 * 32 + 255) / 256, 256>>>(g2_wl, g2_wr, 256, w2hi, w2lo);
    conv_a_kernel<<<(N * 32 + 255) / 256, 256>>>(h1, N, 256, ahi, alo);
    gemm_mma_kernel<<<ggrid, 256>>>(ahi, alo, w2hi, w2lo, g2_bl, g2_br, xl, xr, N, 256);
    edge_csr_kernel<<<eblocks, 256>>>(rowptr, csrc, cea, loopa, xl, xr,
                                      g2_we, g2_att, g2_bias, h2, N);

    // ---- pool + MLP ----
    cudaMemsetAsync(gsum, 0, (size_t)NG_ * 256 * sizeof(float));
    cudaMemsetAsync(gcnt, 0, (size_t)NG_ * sizeof(float));
    pool_kernel<<<(N + 255) / 256, 256>>>(h2, batch, gsum, gcnt, N);
    mlp_kernel<<<NG_, 128>>>(gsum, gcnt, p1_w, p1_b, ln_g, ln_b, p2_w, p2_b, (float*)d_out);
}

// round 13
// speedup vs baseline: 1.6382x; 1.0664x over previous
#include <cuda_runtime.h>
#include <cuda_bf16.h>
#include <cstdint>

#define MAXN 50000
#define MAXE 800000
#define MAXT 391            // ceil(MAXN/128)

// ---------------- device scratch ----------------
__device__ float d_xl[MAXN * 256];
__device__ float d_xr[MAXN * 256];
__device__ float d_h1[MAXN * 256];
__device__ float d_h2[MAXN * 256];
__device__ int   d_cnt[MAXN];
__device__ float d_loopsum[MAXN];
__device__ float d_loopa[MAXN];
__device__ int   d_rowptr[MAXN + 1];
__device__ int   d_pos[MAXN];
__device__ int   d_csrc[MAXE];
__device__ float d_cea[MAXE];
__device__ float d_gsum[64 * 256];
__device__ float d_gcnt[64];
// bf16 hi/lo images, padded to full 128-row tiles
__device__ __align__(16) unsigned short d_ahi[MAXT * 128 * 256];
__device__ __align__(16) unsigned short d_alo[MAXT * 128 * 256];
// transposed combined weights Wt[n][k] (n: 0-255 = wl cols, 256-511 = wr cols)
__device__ __align__(16) unsigned short d_w1hi[512 * 64],  d_w1lo[512 * 64];
__device__ __align__(16) unsigned short d_w2hi[512 * 256], d_w2lo[512 * 256];

// ---------------- helpers ----------------
__device__ __forceinline__ uint32_t smem_u32(const void* p) {
    uint32_t a;
    asm("{ .reg .u64 t; cvta.to.shared.u64 t, %1; cvt.u32.u64 %0, t; }" : "=r"(a) : "l"(p));
    return a;
}
__device__ __forceinline__ void ldsm4(uint32_t* r, uint32_t addr) {
    asm volatile("ldmatrix.sync.aligned.m8n8.x4.shared.b16 {%0,%1,%2,%3}, [%4];"
                 : "=r"(r[0]), "=r"(r[1]), "=r"(r[2]), "=r"(r[3]) : "r"(addr));
}
__device__ __forceinline__ void mma_bf16(float* c, const uint32_t* a, uint32_t b0, uint32_t b1) {
    asm volatile("mma.sync.aligned.m16n8k16.row.col.f32.bf16.bf16.f32 "
                 "{%0,%1,%2,%3}, {%4,%5,%6,%7}, {%8,%9}, {%0,%1,%2,%3};"
                 : "+f"(c[0]), "+f"(c[1]), "+f"(c[2]), "+f"(c[3])
                 : "r"(a[0]), "r"(a[1]), "r"(a[2]), "r"(a[3]), "r"(b0), "r"(b1));
}
__device__ __forceinline__ void cp16(uint32_t saddr, const void* gaddr) {
    asm volatile("cp.async.cg.shared.global [%0], [%1], 16;" :: "r"(saddr), "l"(gaddr));
}
__device__ __forceinline__ void cp_commit() {
    asm volatile("cp.async.commit_group;");
}
template <int Nw>
__device__ __forceinline__ void cp_wait() {
    asm volatile("cp.async.wait_group %0;" :: "n"(Nw));
}
__device__ __forceinline__ void split_bf16(float v, unsigned short& h, unsigned short& l) {
    __nv_bfloat16 hb = __float2bfloat16_rn(v);
    float r = v - __bfloat162float(hb);
    __nv_bfloat16 lb = __float2bfloat16_rn(r);
    h = __bfloat16_as_ushort(hb);
    l = __bfloat16_as_ushort(lb);
}

// ---------------- prep: zero(cnt,loopsum) + encoder->A image + W1 image ----------------
__global__ void prep_kernel(const float* __restrict__ x,
                            const float* __restrict__ enc_w, const float* __restrict__ enc_b,
                            const float* __restrict__ wl, const float* __restrict__ wr,
                            unsigned short* __restrict__ ahi, unsigned short* __restrict__ alo,
                            unsigned short* __restrict__ w1hi, unsigned short* __restrict__ w1lo,
                            int* __restrict__ cnt, float* __restrict__ loopsum, int N) {
    int gid = blockIdx.x * blockDim.x + threadIdx.x;
    int N8 = N * 8;
    if (gid < N8) {
        int i = gid >> 3, g = gid & 7;
        float4 xv = *(const float4*)(x + (size_t)i * 4);
        uint32_t hv[4], lv[4];
#pragma unroll
        for (int q = 0; q < 4; q++) {
            unsigned short hh[2], ll[2];
#pragma unroll
            for (int u = 0; u < 2; u++) {
                int j = g * 8 + q * 2 + u;
                float s = enc_b[j] + xv.x * enc_w[j] + xv.y * enc_w[64 + j]
                        + xv.z * enc_w[128 + j] + xv.w * enc_w[192 + j];
                s = fmaxf(s, 0.f);
                split_bf16(s, hh[u], ll[u]);
            }
            hv[q] = (uint32_t)hh[0] | ((uint32_t)hh[1] << 16);
            lv[q] = (uint32_t)ll[0] | ((uint32_t)ll[1] << 16);
        }
        size_t off = (size_t)i * 64 + g * 8;
        *(uint4*)(ahi + off) = make_uint4(hv[0], hv[1], hv[2], hv[3]);
        *(uint4*)(alo + off) = make_uint4(lv[0], lv[1], lv[2], lv[3]);
        return;
    }
    int gid2 = gid - N8;
    if (gid2 < 4096) {
        int n = gid2 >> 3, g = gid2 & 7;
        int ks = g * 8;
        const float* src = (n < 256) ? wl : wr;
        int col = n & 255;
        uint32_t hv[4], lv[4];
#pragma unroll
        for (int q = 0; q < 4; q++) {
            float v0 = src[(size_t)(ks + 2 * q) * 256 + col];
            float v1 = src[(size_t)(ks + 2 * q + 1) * 256 + col];
            unsigned short h0, l0, h1, l1;
            split_bf16(v0, h0, l0);
            split_bf16(v1, h1, l1);
            hv[q] = (uint32_t)h0 | ((uint32_t)h1 << 16);
            lv[q] = (uint32_t)l0 | ((uint32_t)l1 << 16);
        }
        size_t off = (size_t)n * 64 + ks;
        *(uint4*)(w1hi + off) = make_uint4(hv[0], hv[1], hv[2], hv[3]);
        *(uint4*)(w1lo + off) = make_uint4(lv[0], lv[1], lv[2], lv[3]);
        return;
    }
    int gid3 = gid2 - 4096;
    if (gid3 < N) {
        cnt[gid3] = 0;
        loopsum[gid3] = 0.f;
    }
}

// ---------------- CSR build ----------------
__global__ void count_kernel(const int* __restrict__ ei, const float* __restrict__ eattr,
                             int* __restrict__ cnt, float* __restrict__ loopsum, int E) {
    int e = blockIdx.x * blockDim.x + threadIdx.x;
    if (e >= E) return;
    int dst = ei[E + e];
    atomicAdd(cnt + dst, 1);
    atomicAdd(loopsum + dst, eattr[e]);
}

__global__ __launch_bounds__(1024) void scan_kernel(
    const int* __restrict__ cnt, const float* __restrict__ loopsum,
    int* __restrict__ rowptr, int* __restrict__ pos, float* __restrict__ loopa,
    int N, int E) {
    __shared__ int part[1024];
    int t = threadIdx.x;
    int chunk = (N + 1023) / 1024;
    int b0 = t * chunk, b1 = min(b0 + chunk, N);
    int s = 0;
    for (int j = b0; j < b1; j++) s += cnt[j];
    part[t] = s;
    __syncthreads();
    for (int off = 1; off < 1024; off <<= 1) {
        int v = (t >= off) ? part[t - off] : 0;
        __syncthreads();
        part[t] += v;
        __syncthreads();
    }
    int run = (t == 0) ? 0 : part[t - 1];
    for (int j = b0; j < b1; j++) {
        rowptr[j] = run;
        pos[j] = run;
        int c = cnt[j];
        loopa[j] = loopsum[j] / (float)max(c, 1);
        run += c;
    }
    if (t == 1023) rowptr[N] = E;
}

__global__ void scatter_kernel(const int* __restrict__ ei, const float* __restrict__ eattr,
                               int* __restrict__ pos,
                               int* __restrict__ csrc, float* __restrict__ cea, int E) {
    int e = blockIdx.x * blockDim.x + threadIdx.x;
    if (e >= E) return;
    int dst = ei[E + e];
    int p = atomicAdd(pos + dst, 1);
    csrc[p] = ei[e];
    cea[p] = eattr[e];
}

// ---------------- A fp32 [M,K] -> bf16 hi/lo (row-major) ----------------
__global__ void conv_a_kernel(const float* __restrict__ A, int M, int K,
                              unsigned short* __restrict__ hi, unsigned short* __restrict__ lo) {
    int total = M * (K >> 3);
    int gid = blockIdx.x * blockDim.x + threadIdx.x;
    if (gid >= total) return;
    size_t off = (size_t)gid * 8;
    float4 f0 = *(const float4*)(A + off);
    float4 f1 = *(const float4*)(A + off + 4);
    float v[8] = {f0.x, f0.y, f0.z, f0.w, f1.x, f1.y, f1.z, f1.w};
    uint32_t hv[4], lv[4];
#pragma unroll
    for (int q = 0; q < 4; q++) {
        unsigned short h0, l0, h1, l1;
        split_bf16(v[2 * q], h0, l0);
        split_bf16(v[2 * q + 1], h1, l1);
        hv[q] = (uint32_t)h0 | ((uint32_t)h1 << 16);
        lv[q] = (uint32_t)l0 | ((uint32_t)l1 << 16);
    }
    *(uint4*)(hi + off) = make_uint4(hv[0], hv[1], hv[2], hv[3]);
    *(uint4*)(lo + off) = make_uint4(lv[0], lv[1], lv[2], lv[3]);
}

// ---------------- W [K,256] x2 -> combined transposed Wt[n][k] bf16 hi/lo ----------------
__global__ void conv_w_kernel(const float* __restrict__ wl, const float* __restrict__ wr,
                              int K,
                              unsigned short* __restrict__ hi, unsigned short* __restrict__ lo) {
    int gpr = K >> 3;
    int total = 512 * gpr;
    int gid = blockIdx.x * blockDim.x + threadIdx.x;
    if (gid >= total) return;
    int n = gid / gpr, g = gid % gpr;
    int ks = g * 8;
    const float* src = (n < 256) ? wl : wr;
    int col = n & 255;
    uint32_t hv[4], lv[4];
#pragma unroll
    for (int q = 0; q < 4; q++) {
        float v0 = src[(size_t)(ks + 2 * q) * 256 + col];
        float v1 = src[(size_t)(ks + 2 * q + 1) * 256 + col];
        unsigned short h0, l0, h1, l1;
        split_bf16(v0, h0, l0);
        split_bf16(v1, h1, l1);
        hv[q] = (uint32_t)h0 | ((uint32_t)h1 << 16);
        lv[q] = (uint32_t)l0 | ((uint32_t)l1 << 16);
    }
    size_t off = (size_t)n * K + ks;
    *(uint4*)(hi + off) = make_uint4(hv[0], hv[1], hv[2], hv[3]);
    *(uint4*)(lo + off) = make_uint4(lv[0], lv[1], lv[2], lv[3]);
}

// ---------------- mma.sync dual GEMM, cp.async double-buffered, 2 CTA/SM ----------------
#define SROW 24   // ushorts per smem row (48B stride, conflict-free for ldmatrix)
__global__ __launch_bounds__(256, 2) void gemm_mma_kernel(
    const unsigned short* __restrict__ ahi, const unsigned short* __restrict__ alo,
    const unsigned short* __restrict__ whi, const unsigned short* __restrict__ wlo,
    const float* __restrict__ bl, const float* __restrict__ br,
    float* __restrict__ xl, float* __restrict__ xr, int M, int K) {
    __shared__ __align__(16) unsigned short sAh[2][128 * SROW], sAl[2][128 * SROW];
    __shared__ __align__(16) unsigned short sBh[2][128 * SROW], sBl[2][128 * SROW];

    int tid = threadIdx.x, lane = tid & 31, wid = tid >> 5;
    int wm = wid & 3, wn = wid >> 2;
    int row0 = blockIdx.y * 128, bn0 = blockIdx.x * 128;

    float acc[2][8][4];
#pragma unroll
    for (int t = 0; t < 2; t++)
#pragma unroll
        for (int j = 0; j < 8; j++)
#pragma unroll
            for (int q = 0; q < 4; q++) acc[t][j][q] = 0.f;

    int srow = tid >> 1, kh = (tid & 1) << 3;
    uint32_t soff = (uint32_t)((srow * 3 + (tid & 1)) * 16);
    const int nstage = K >> 4;

    uint32_t bAh[2] = {smem_u32(sAh[0]), smem_u32(sAh[1])};
    uint32_t bAl[2] = {smem_u32(sAl[0]), smem_u32(sAl[1])};
    uint32_t bBh[2] = {smem_u32(sBh[0]), smem_u32(sBh[1])};
    uint32_t bBl[2] = {smem_u32(sBl[0]), smem_u32(sBl[1])};

    uint32_t aoff = (uint32_t)((lane & 15) * 48 + ((lane >> 4) << 4));
    uint32_t boff = (uint32_t)((((lane >> 4) << 3) + (lane & 7)) * 48 + (((lane >> 3) & 1) << 4));

    size_t gA = (size_t)(row0 + srow) * K + kh;
    size_t gB = (size_t)(bn0 + srow) * K + kh;

    auto issue = [&](int s, int b) {
        size_t o = (size_t)s * 16;
        cp16(bAh[b] + soff, ahi + gA + o);
        cp16(bAl[b] + soff, alo + gA + o);
        cp16(bBh[b] + soff, whi + gB + o);
        cp16(bBl[b] + soff, wlo + gB + o);
        cp_commit();
    };

    issue(0, 0);

    for (int s = 0; s < nstage; s++) {
        int buf = s & 1;
        if (s + 1 < nstage) {
            issue(s + 1, buf ^ 1);
            cp_wait<1>();
        } else {
            cp_wait<0>();
        }
        __syncthreads();

        uint32_t a_hi[2][4], a_lo[2][4];
#pragma unroll
        for (int t = 0; t < 2; t++) {
            uint32_t ra = (uint32_t)((wm * 32 + t * 16) * 48);
            ldsm4(a_hi[t], bAh[buf] + ra + aoff);
            ldsm4(a_lo[t], bAl[buf] + ra + aoff);
        }
#pragma unroll
        for (int bp = 0; bp < 4; bp++) {
            uint32_t rb = (uint32_t)((wn * 64 + bp * 16) * 48);
            uint32_t bh[4], blo[4];
            ldsm4(bh, bBh[buf] + rb + boff);
            ldsm4(blo, bBl[buf] + rb + boff);
#pragma unroll
            for (int t = 0; t < 2; t++) {
                mma_bf16(acc[t][2 * bp],     a_hi[t], bh[0], bh[1]);
                mma_bf16(acc[t][2 * bp + 1], a_hi[t], bh[2], bh[3]);
                mma_bf16(acc[t][2 * bp],     a_lo[t], bh[0], bh[1]);
                mma_bf16(acc[t][2 * bp + 1], a_lo[t], bh[2], bh[3]);
                mma_bf16(acc[t][2 * bp],     a_hi[t], blo[0], blo[1]);
                mma_bf16(acc[t][2 * bp + 1], a_hi[t], blo[2], blo[3]);
            }
        }
        __syncthreads();
    }

    // epilogue
#pragma unroll
    for (int t = 0; t < 2; t++) {
#pragma unroll
        for (int j = 0; j < 8; j++) {
            int gc = bn0 + wn * 64 + j * 8 + ((lane & 3) << 1);
            int cc = (gc < 256) ? gc : gc - 256;
            float* base = (gc < 256) ? xl : xr;
            const float* bias = (gc < 256) ? bl : br;
            float b0 = bias[cc], b1 = bias[cc + 1];
#pragma unroll
            for (int h = 0; h < 2; h++) {
                int gm = row0 + wm * 32 + t * 16 + (lane >> 2) + h * 8;
                if (gm < M) {
                    float2 v = make_float2(acc[t][j][2 * h] + b0, acc[t][j][2 * h + 1] + b1);
                    *(float2*)(base + (size_t)gm * 256 + cc) = v;
                }
            }
        }
    }
}

// ---------------- CSR edge pass: per-warp cp.async ring (depth 4), fully fused ----------------
#define EDEPTH 4
__global__ __launch_bounds__(256) void edge_csr_kernel(
    const int* __restrict__ rowptr, const int* __restrict__ csrc,
    const float* __restrict__ cea, const float* __restrict__ loopa,
    const float* __restrict__ xl, const float* __restrict__ xr,
    const float* __restrict__ we, const float* __restrict__ att,
    const float* __restrict__ bias, float* __restrict__ out, int N) {
    __shared__ __align__(16) float ring[8][EDEPTH][256];   // 32KB
    int lane = threadIdx.x & 31;
    int wib = threadIdx.x >> 5;
    int warp = (blockIdx.x * blockDim.x + threadIdx.x) >> 5;
    int nw = (gridDim.x * blockDim.x) >> 5;
    int c0 = lane << 3;
    float wef[8], attf[8], bf[8];
#pragma unroll
    for (int q = 0; q < 8; q++) {
        wef[q] = we[c0 + q]; attf[q] = att[c0 + q]; bf[q] = bias[c0 + q];
    }
    uint32_t ringbase = smem_u32(&ring[wib][0][0]);
    uint32_t myoff = (uint32_t)(lane * 32);    // this lane's 32 bytes within a slot

    for (int i = warp; i < N; i += nw) {
        const float* pr = xr + (size_t)i * 256 + c0;
        float4 r0 = *(const float4*)pr;
        float4 r1 = *(const float4*)(pr + 4);
        float rv[8] = {r0.x, r0.y, r0.z, r0.w, r1.x, r1.y, r1.z, r1.w};
        float acc[8] = {0, 0, 0, 0, 0, 0, 0, 0};
        float den = 0.f;

        int rb = rowptr[i];
        int deg = rowptr[i + 1] - rb;
        int total = deg + 1;               // + self loop (edge index 'deg')
        float la = loopa[i];

        auto issue = [&](int k) {
            if (k < total) {
                int s = (k < deg) ? __ldg(csrc + rb + k) : i;
                const float* p = xl + (size_t)s * 256 + c0;
                uint32_t dst = ringbase + (uint32_t)((k & (EDEPTH - 1)) * 1024) + myoff;
                cp16(dst, p);
                cp16(dst + 16, p + 4);
            }
            cp_commit();                   // always commit (empty groups keep count exact)
        };
        issue(0); issue(1); issue(2); issue(3);

        for (int k = 0; k < total; k++) {
            cp_wait<EDEPTH - 1>();         // edge k's group complete
            float ea = (k < deg) ? __ldg(cea + rb + k) : la;
            const float* slot = &ring[wib][k & (EDEPTH - 1)][c0];
            float4 A0 = *(const float4*)slot;
            float4 A1 = *(const float4*)(slot + 4);
            float lv[8] = {A0.x, A0.y, A0.z, A0.w, A1.x, A1.y, A1.z, A1.w};
            float a = 0.f;
#pragma unroll
            for (int q = 0; q < 8; q++) {
                float m = lv[q] + rv[q] + ea * wef[q];
                m = (m > 0.f) ? m : 0.2f * m;   // leaky_relu 0.2
                a += m * attf[q];
            }
            a += __shfl_xor_sync(0xffffffffu, a, 1);
            a += __shfl_xor_sync(0xffffffffu, a, 2);
            a += __shfl_xor_sync(0xffffffffu, a, 4);
            float ex = __expf(a);          // softmax shift-invariant; alpha small
            den += ex;
#pragma unroll
            for (int q = 0; q < 8; q++) acc[q] += ex * lv[q];
            issue(k + EDEPTH);             // refill slot just consumed
        }

        float inv = 1.0f / den;
        float o[8];
#pragma unroll
        for (int q = 0; q < 8; q++) o[q] = fmaxf(acc[q] * inv + bf[q], 0.f);
        float* po = out + (size_t)i * 256 + c0;
        *(float4*)(po)     = *(float4*)(o);
        *(float4*)(po + 4) = *(float4*)(o + 4);
    }
}

// ---------------- global mean pool ----------------
__global__ __launch_bounds__(256) void pool_kernel(
    const float* __restrict__ h, const int* __restrict__ batch,
    float* __restrict__ gsum, float* __restrict__ gcnt, int N) {
    __shared__ int sb[256];
    int t = threadIdx.x;
    int start = blockIdx.x * 256;
    int end = min(start + 256, N);
    int n = end - start;
    if (n <= 0) return;
    if (t < n) sb[t] = batch[start + t];
    __syncthreads();
    float acc = 0.f, cnt = 0.f;
    int cur = sb[0];
    for (int i = 0; i < n; i++) {
        int b = sb[i];
        if (b != cur) {
            atomicAdd(gsum + (size_t)cur * 256 + t, acc);
            if (t == 0) atomicAdd(gcnt + cur, cnt);
            acc = 0.f; cnt = 0.f; cur = b;
        }
        acc += h[(size_t)(start + i) * 256 + t];
        cnt += 1.f;
    }
    atomicAdd(gsum + (size_t)cur * 256 + t, acc);
    if (t == 0) atomicAdd(gcnt + cur, cnt);
}

// ---------------- final MLP ----------------
__global__ __launch_bounds__(128) void mlp_kernel(
    const float* __restrict__ gsum, const float* __restrict__ gcnt,
    const float* __restrict__ p1w, const float* __restrict__ p1b,
    const float* __restrict__ lng, const float* __restrict__ lnb,
    const float* __restrict__ p2w, const float* __restrict__ p2b,
    float* __restrict__ out) {
    __shared__ float gs[256];
    __shared__ float zs[128];
    __shared__ float wsum[4], wsum2[4];
    int b = blockIdx.x, t = threadIdx.x;
    float invc = 1.0f / fmaxf(gcnt[b], 1.0f);
    gs[t] = gsum[(size_t)b * 256 + t] * invc;
    gs[t + 128] = gsum[(size_t)b * 256 + 128 + t] * invc;
    __syncthreads();
    float z = p1b[t];
    for (int k = 0; k < 256; k++) z += gs[k] * p1w[(size_t)k * 128 + t];
    float s = z, s2 = z * z;
#pragma unroll
    for (int o = 16; o; o >>= 1) {
        s += __shfl_xor_sync(0xffffffffu, s, o);
        s2 += __shfl_xor_sync(0xffffffffu, s2, o);
    }
    if ((t & 31) == 0) { wsum[t >> 5] = s; wsum2[t >> 5] = s2; }
    __syncthreads();
    s = wsum[0] + wsum[1] + wsum[2] + wsum[3];
    s2 = wsum2[0] + wsum2[1] + wsum2[2] + wsum2[3];
    float mu = s * (1.0f / 128.0f);
    float var = s2 * (1.0f / 128.0f) - mu * mu;
    float zn = (z - mu) * rsqrtf(var + 1e-5f) * lng[t] + lnb[t];
    zs[t] = fmaxf(zn, 0.f);
    __syncthreads();
    if (t < 64) {
        float o = p2b[t];
        for (int j = 0; j < 128; j++) o += zs[j] * p2w[(size_t)j * 64 + t];
        out[(size_t)b * 64 + t] = fmaxf(o, 0.f);
    }
}

extern "C" void kernel_launch(void* const* d_in, const int* in_sizes, int n_in,
                              void* d_out, int out_size) {
    const float* x      = (const float*)d_in[0];
    const int*   ei     = (const int*)d_in[1];
    const float* eattr  = (const float*)d_in[2];
    const int*   batch  = (const int*)d_in[3];
    const float* enc_w  = (const float*)d_in[4];
    const float* enc_b  = (const float*)d_in[5];
    const float* g1_wl  = (const float*)d_in[6];
    const float* g1_bl  = (const float*)d_in[7];
    const float* g1_wr  = (const float*)d_in[8];
    const float* g1_br  = (const float*)d_in[9];
    const float* g1_we  = (const float*)d_in[10];
    const float* g1_att = (const float*)d_in[11];
    const float* g1_bias= (const float*)d_in[12];
    const float* g2_wl  = (const float*)d_in[13];
    const float* g2_bl  = (const float*)d_in[14];
    const float* g2_wr  = (const float*)d_in[15];
    const float* g2_br  = (const float*)d_in[16];
    const float* g2_we  = (const float*)d_in[17];
    const float* g2_att = (const float*)d_in[18];
    const float* g2_bias= (const float*)d_in[19];
    const float* p1_w   = (const float*)d_in[20];
    const float* p1_b   = (const float*)d_in[21];
    const float* ln_g   = (const float*)d_in[22];
    const float* ln_b   = (const float*)d_in[23];
    const float* p2_w   = (const float*)d_in[24];
    const float* p2_b   = (const float*)d_in[25];

    int N = in_sizes[3];
    int E = in_sizes[2];
    int NG_ = out_size / 64;

    float *xl, *xr, *h1, *h2, *loopsum, *loopa, *cea, *gsum, *gcnt;
    int *cnt, *rowptr, *pos, *csrc;
    unsigned short *ahi, *alo, *w1hi, *w1lo, *w2hi, *w2lo;
    cudaGetSymbolAddress((void**)&xl, d_xl);
    cudaGetSymbolAddress((void**)&xr, d_xr);
    cudaGetSymbolAddress((void**)&h1, d_h1);
    cudaGetSymbolAddress((void**)&h2, d_h2);
    cudaGetSymbolAddress((void**)&cnt, d_cnt);
    cudaGetSymbolAddress((void**)&loopsum, d_loopsum);
    cudaGetSymbolAddress((void**)&loopa, d_loopa);
    cudaGetSymbolAddress((void**)&rowptr, d_rowptr);
    cudaGetSymbolAddress((void**)&pos, d_pos);
    cudaGetSymbolAddress((void**)&csrc, d_csrc);
    cudaGetSymbolAddress((void**)&cea, d_cea);
    cudaGetSymbolAddress((void**)&gsum, d_gsum);
    cudaGetSymbolAddress((void**)&gcnt, d_gcnt);
    cudaGetSymbolAddress((void**)&ahi, d_ahi);
    cudaGetSymbolAddress((void**)&alo, d_alo);
    cudaGetSymbolAddress((void**)&w1hi, d_w1hi);
    cudaGetSymbolAddress((void**)&w1lo, d_w1lo);
    cudaGetSymbolAddress((void**)&w2hi, d_w2hi);
    cudaGetSymbolAddress((void**)&w2lo, d_w2lo);

    int ntiles = (N + 127) / 128;
    int eblocks = (N * 32 + 255) / 256;
    dim3 ggrid(4, ntiles);

    // Launch order puts the layer-1 edge_csr_kernel at index 5 (ncu captures -s 5 -c 1).
    int preptot = N * 8 + 4096 + N;
    prep_kernel<<<(preptot + 255) / 256, 256>>>(x, enc_w, enc_b, g1_wl, g1_wr,
                                                ahi, alo, w1hi, w1lo, cnt, loopsum, N); // 0
    count_kernel<<<(E + 255) / 256, 256>>>(ei, eattr, cnt, loopsum, E);                 // 1
    scan_kernel<<<1, 1024>>>(cnt, loopsum, rowptr, pos, loopa, N, E);                   // 2
    scatter_kernel<<<(E + 255) / 256, 256>>>(ei, eattr, pos, csrc, cea, E);             // 3
    gemm_mma_kernel<<<ggrid, 256>>>(ahi, alo, w1hi, w1lo, g1_bl, g1_br, xl, xr, N, 64); // 4
    edge_csr_kernel<<<eblocks, 256>>>(rowptr, csrc, cea, loopa, xl, xr,
                                      g1_we, g1_att, g1_bias, h1, N);                   // 5 <- profiled

    // ---- GAT layer 2 (K = 256) ----
    conv_w_kernel<<<(512 * 32 + 255) / 256, 256>>>(g2_wl, g2_wr, 256, w2hi, w2lo);
    conv_a_kernel<<<(N * 32 + 255) / 256, 256>>>(h1, N, 256, ahi, alo);
    gemm_mma_kernel<<<ggrid, 256>>>(ahi, alo, w2hi, w2lo, g2_bl, g2_br, xl, xr, N, 256);
    edge_csr_kernel<<<eblocks, 256>>>(rowptr, csrc, cea, loopa, xl, xr,
                                      g2_we, g2_att, g2_bias, h2, N);

    // ---- pool + MLP ----
    cudaMemsetAsync(gsum, 0, (size_t)NG_ * 256 * sizeof(float));
    cudaMemsetAsync(gcnt, 0, (size_t)NG_ * sizeof(float));
    pool_kernel<<<(N + 255) / 256, 256>>>(h2, batch, gsum, gcnt, N);
    mlp_kernel<<<NG_, 128>>>(gsum, gcnt, p1_w, p1_b, ln_g, ln_b, p2_w, p2_b, (float*)d_out);
}